// round 10
// baseline (speedup 1.0000x reference)
#include <cuda_runtime.h>
#include <cuda_bf16.h>
#include <cuda_fp16.h>
#include <cstdint>
#include <math.h>

// Problem constants (fixed shapes)
#define BB      4
#define NQ      900
#define DD      256
#define CH      256
#define HH      200
#define WW      200
#define HWSZ    40000
#define NHEADS  8
#define HDIM    32
#define NK      10
#define NPTS    4

// ---------------- scratch (device globals; no runtime allocation) ----------------
__device__ float g_q  [BB * NQ * DD];
__device__ __half g_vh[(long)BB * HWSZ * DD];    // projected BEV values (fp16)
__device__ float g_oa [BB * NQ * 128];           // fused offsets(64)+attn logits(32)+pad
__device__ float g_s  [BB * NQ * DD];
__device__ float g_t  [BB * NQ * DD];
__device__ __half g_bhi[DD * CH];                // WvT [n][k] fp16
__device__ float g_woa[DD * 128];                // packed [Woff | Wattn | 0] fp32 [k][n]
__device__ float g_wf [DD * 128];                // Wq @ woa  [k][n]
__device__ float g_bf [128];                     // bq @ woa + [boff|battn|0]
__device__ float g_zero[128];                    // stays zero

// ---------------- helpers ----------------
__device__ __forceinline__ uint32_t smem_u32(const void* p) {
    uint32_t a;
    asm("{ .reg .u64 t; cvta.to.shared.u64 t, %1; cvt.u32.u64 %0, t; }" : "=r"(a) : "l"(p));
    return a;
}
__device__ __forceinline__ uint32_t bf2u(__nv_bfloat16 a, __nv_bfloat16 b) {
    __nv_bfloat162 t(a, b);
    return *reinterpret_cast<uint32_t*>(&t);
}
__device__ __forceinline__ uint32_t h2u(__half a, __half b) {
    __half2 t(a, b);
    return *reinterpret_cast<uint32_t*>(&t);
}

#define LDSM_T(r, addr) \
    asm volatile("ldmatrix.sync.aligned.m8n8.x4.trans.shared.b16 {%0,%1,%2,%3}, [%4];" \
        : "=r"((r)[0]), "=r"((r)[1]), "=r"((r)[2]), "=r"((r)[3]) : "r"(addr))
#define LDSM(r, addr) \
    asm volatile("ldmatrix.sync.aligned.m8n8.x4.shared.b16 {%0,%1,%2,%3}, [%4];" \
        : "=r"((r)[0]), "=r"((r)[1]), "=r"((r)[2]), "=r"((r)[3]) : "r"(addr))
#define MMA_BF16(c, a, b0, b1) \
    asm volatile("mma.sync.aligned.m16n8k16.row.col.f32.bf16.bf16.f32 " \
        "{%0,%1,%2,%3},{%4,%5,%6,%7},{%8,%9},{%0,%1,%2,%3};" \
        : "+f"((c)[0]), "+f"((c)[1]), "+f"((c)[2]), "+f"((c)[3]) \
        : "r"((a)[0]), "r"((a)[1]), "r"((a)[2]), "r"((a)[3]), "r"(b0), "r"(b1))
#define MMA_F16(c, a, b0, b1) \
    asm volatile("mma.sync.aligned.m16n8k16.row.col.f32.f16.f16.f32 " \
        "{%0,%1,%2,%3},{%4,%5,%6,%7},{%8,%9},{%0,%1,%2,%3};" \
        : "+f"((c)[0]), "+f"((c)[1]), "+f"((c)[2]), "+f"((c)[3]) \
        : "r"((a)[0]), "r"((a)[1]), "r"((a)[2]), "r"((a)[3]), "r"(b0), "r"(b1))
#define CP16(dst, src) \
    asm volatile("cp.async.cg.shared.global [%0], [%1], 16;" :: "r"(dst), "l"(src))
#define CP_COMMIT()  asm volatile("cp.async.commit_group;" ::: "memory")
#define CP_WAIT0()   asm volatile("cp.async.wait_group 0;" ::: "memory")

__device__ __forceinline__ void split_store(char* dst_h, char* dst_l, uint32_t off, float4 v) {
    __nv_bfloat16 h0 = __float2bfloat16(v.x), h1 = __float2bfloat16(v.y);
    __nv_bfloat16 h2 = __float2bfloat16(v.z), h3 = __float2bfloat16(v.w);
    __nv_bfloat16 l0 = __float2bfloat16(v.x - __bfloat162float(h0));
    __nv_bfloat16 l1 = __float2bfloat16(v.y - __bfloat162float(h1));
    __nv_bfloat16 l2 = __float2bfloat16(v.z - __bfloat162float(h2));
    __nv_bfloat16 l3 = __float2bfloat16(v.w - __bfloat162float(h3));
    *(uint2*)(dst_h + off) = make_uint2(bf2u(h0, h1), bf2u(h2, h3));
    *(uint2*)(dst_l + off) = make_uint2(bf2u(l0, l1), bf2u(l2, l3));
}

// ---------------- Wv (K=256, N=256) -> WvT fp16 [n][k] ----------------
__global__ __launch_bounds__(256) void conv_wv(const float* __restrict__ Wv)
{
    int idx = blockIdx.x * 256 + threadIdx.x;   // n*256 + k
    int n = idx >> 8, k = idx & 255;
    g_bhi[idx] = __float2half(Wv[k * DD + n]);
}

// ---------------- pack [Woff | Wattn | 0] -> g_woa [256][128] ----------------
__global__ __launch_bounds__(256) void pack_woa(
    const float* __restrict__ Woff, const float* __restrict__ Wattn)
{
    int idx = blockIdx.x * 256 + threadIdx.x;   // 0..32767
    int k = idx >> 7, n = idx & 127;
    float v = (n < 64) ? Woff[k * 64 + n] : (n < 96 ? Wattn[k * 32 + (n - 64)] : 0.f);
    g_woa[idx] = v;
}

// ---------------- g_bf = bq @ g_woa + [boff|battn|0] ----------------
__global__ __launch_bounds__(128) void bias_f_kernel(
    const float* __restrict__ bq, const float* __restrict__ boff,
    const float* __restrict__ battn)
{
    int n = threadIdx.x;
    float s = (n < 64) ? boff[n] : (n < 96 ? battn[n - 64] : 0.f);
#pragma unroll 8
    for (int k = 0; k < 256; k++) s = fmaf(bq[k], g_woa[k * 128 + n], s);
    g_bf[n] = s;
}

// =====================================================================
// gemm_v: v[b,m,:] = bev^T[b,m,:] @ WvT^T + bv  (HMMA fp16 x fp16, fp32 acc)
// =====================================================================
#define VA_OFF        0                                     // 32768 bytes
#define VB(buf)       (32768 + (buf) * 16384)               // ..65536
#define V_STG         32768                                 // epilogue stage
#define V_SMEM 66560

__global__ void __launch_bounds__(256, 2) gemm_v(
    const float* __restrict__ bev, const float* __restrict__ bias)
{
    extern __shared__ char smem[];
    const uint32_t sb = smem_u32(smem);
    const int tid = threadIdx.x;
    const int lane = tid & 31;
    const int wid = tid >> 5;
    const int warp_m = wid & 1;
    const int warp_n = wid >> 1;
    const int m0 = blockIdx.x * 64;
    const int b = blockIdx.y;

    const float* Ag = bev + (long)b * CH * HWSZ + m0;

    uint32_t b_dst_off[4], b_goff[4];
#pragma unroll
    for (int p = 0; p < 4; p++) {
        int e = tid + p * 256;
        int n = e >> 2, c = e & 3;
        b_dst_off[p] = (uint32_t)(n * 64 + ((c ^ ((n >> 1) & 3)) << 4));
        b_goff[p] = (uint32_t)(n * 256 + c * 8);
    }

#pragma unroll
    for (int p = 0; p < 4; p++)
        CP16(sb + VB(0) + b_dst_off[p], (const void*)(g_bhi + b_goff[p]));
    CP_COMMIT();

#pragma unroll 4
    for (int p = 0; p < 16; p++) {
        int idx = tid + p * 256;
        int k = idx >> 4;
        int m4 = (idx & 15) << 2;
        float4 v = *(const float4*)(Ag + (long)k * HWSZ + m4);
        int c = m4 >> 3;
        uint32_t off = (uint32_t)(k * 128 + ((c ^ (k & 7)) << 4) + ((m4 & 4) << 1));
        *(uint2*)(smem + VA_OFF + off) = make_uint2(
            h2u(__float2half(v.x), __float2half(v.y)),
            h2u(__float2half(v.z), __float2half(v.w)));
    }

    const int tile = lane >> 3;
    const int kl = (lane & 7) + ((tile & 2) << 2);
    uint32_t aoff[2];
#pragma unroll
    for (int mf = 0; mf < 2; mf++) {
        int c = (warp_m * 32 + mf * 16 + ((tile & 1) << 3)) >> 3;
        aoff[mf] = (uint32_t)(kl * 128 + (((c ^ (kl & 7)) & 7) << 4));
    }
    uint32_t boff[4];
#pragma unroll
    for (int q = 0; q < 4; q++) {
        int n = warp_n * 64 + q * 16 + ((tile & 1) << 3) + (lane & 7);
        int c = (tile & 2) >> 1;
        boff[q] = (uint32_t)(n * 64 + ((c ^ ((n >> 1) & 3)) << 4));
    }

    float acc[2][8][4];
#pragma unroll
    for (int i = 0; i < 2; i++)
#pragma unroll
        for (int j = 0; j < 8; j++)
#pragma unroll
            for (int r = 0; r < 4; r++) acc[i][j][r] = 0.f;

    CP_WAIT0();
    __syncthreads();

    for (int kc = 0; kc < 8; kc++) {
        const int cur = kc & 1;
        if (kc < 7) {
            const uint32_t k0 = (uint32_t)((kc + 1) * 32);
#pragma unroll
            for (int p = 0; p < 4; p++)
                CP16(sb + VB(1 - cur) + b_dst_off[p], (const void*)(g_bhi + b_goff[p] + k0));
            CP_COMMIT();
        }

        const uint32_t Bh = sb + VB(cur);
#pragma unroll
        for (int ks = 0; ks < 2; ks++) {
            uint32_t a[2][4];
            const uint32_t akc = (uint32_t)((kc * 32 + ks * 16) * 128);
#pragma unroll
            for (int mf = 0; mf < 2; mf++)
                LDSM_T(a[mf], sb + VA_OFF + akc + aoff[mf]);

            const uint32_t ksx = (uint32_t)(ks << 5);
            uint32_t bh[2][4];
            LDSM(bh[0], Bh + (boff[0] ^ ksx));
#pragma unroll
            for (int q = 0; q < 4; q++) {
                const int bc = q & 1, bn_ = bc ^ 1;
                if (q < 3)
                    LDSM(bh[bn_], Bh + (boff[q + 1] ^ ksx));
#pragma unroll
                for (int h = 0; h < 2; h++) {
                    const int nf = q * 2 + h;
#pragma unroll
                    for (int mf = 0; mf < 2; mf++)
                        MMA_F16(acc[mf][nf], a[mf], bh[bc][h], bh[bc][h + 2]);
                }
            }
        }

        if (kc < 7) CP_WAIT0();
        __syncthreads();
    }

    char* stg = smem + V_STG;
#pragma unroll
    for (int mf = 0; mf < 2; mf++) {
        int mrow = warp_m * 32 + mf * 16 + (lane >> 2);
#pragma unroll
        for (int nf = 0; nf < 8; nf++) {
            int n = warp_n * 64 + nf * 8 + (lane & 3) * 2;
            float2 bb = *(const float2*)(bias + n);
            __half2 v0 = __floats2half2_rn(acc[mf][nf][0] + bb.x, acc[mf][nf][1] + bb.y);
            __half2 v1 = __floats2half2_rn(acc[mf][nf][2] + bb.x, acc[mf][nf][3] + bb.y);
            *(__half2*)(stg + mrow * 528 + n * 2) = v0;
            *(__half2*)(stg + (mrow + 8) * 528 + n * 2) = v1;
        }
    }
    __syncthreads();
    __half* vout = g_vh + ((long)b * HWSZ + m0) * DD;
#pragma unroll
    for (int i = 0; i < 8; i++) {
        int cid = tid + i * 256;
        int r = cid >> 5, c16 = cid & 31;
        *(uint4*)((char*)vout + (long)r * 512 + c16 * 16) =
            *(const uint4*)(stg + r * 528 + c16 * 16);
    }
}

// =====================================================================
// gemm_core: C[m0.., n0..n0+128] = A[M x 256] @ B[256 x ldb] + bias (+R)
// bf16 3-term split, CTA 64 x 128, 8 warps = 2m x 4n.
// =====================================================================
#define S_APITCH 72
#define S_BPITCH 136
#define S_ASZ    (64 * S_APITCH * 2)            // 9216
#define S_BSZ    (64 * S_BPITCH * 2)            // 17408
#define S_AB(buf, hl) (((buf) * 2 + (hl)) * S_ASZ)               // 0..36864
#define S_BB(buf, hl) (36864 + ((buf) * 2 + (hl)) * S_BSZ)       // ..106496
#define S_SMEM 106496

template <bool RES>
__device__ __forceinline__ void gemm_core(
    const float* __restrict__ A, const float* __restrict__ Bm,
    const float* __restrict__ bias, const float* __restrict__ Rm,
    float* __restrict__ C, int M, int n0, int m0, int ldb, int ldc,
    char* smem)
{
    const uint32_t sb = smem_u32(smem);
    const int tid = threadIdx.x;
    const int lane = tid & 31;
    const int wid = tid >> 5;
    const int warp_m = wid & 1;
    const int warp_n = wid >> 1;

    const int tile = lane >> 3;
    uint32_t aoff[2];
#pragma unroll
    for (int mf = 0; mf < 2; mf++) {
        int ml = warp_m * 32 + mf * 16 + ((tile & 1) << 3) + (lane & 7);
        int kcol = (tile & 2) << 2;
        aoff[mf] = (uint32_t)(ml * S_APITCH + kcol) * 2;
    }
    uint32_t boff[2];
#pragma unroll
    for (int q = 0; q < 2; q++) {
        int kr = (lane & 7) + ((tile & 2) << 2);
        int nc = warp_n * 32 + q * 16 + ((tile & 1) << 3);
        boff[q] = (uint32_t)(kr * S_BPITCH + nc) * 2;
    }

    float acc[2][4][4];
#pragma unroll
    for (int i = 0; i < 2; i++)
#pragma unroll
        for (int j = 0; j < 4; j++)
#pragma unroll
            for (int r = 0; r < 4; r++) acc[i][j][r] = 0.f;

    float4 rA[4], rB[8];

    auto g_load = [&](int kc) {
        const int k0 = kc * 64;
#pragma unroll
        for (int p = 0; p < 4; p++) {
            int idx = tid + p * 256;
            int m = idx >> 4, k4 = (idx & 15) << 2;
            rA[p] = (m0 + m < M) ? *(const float4*)(A + (long)(m0 + m) * DD + k0 + k4)
                                 : make_float4(0.f, 0.f, 0.f, 0.f);
        }
#pragma unroll
        for (int p = 0; p < 8; p++) {
            int idx = tid + p * 256;
            int k = idx >> 5, n4 = (idx & 31) << 2;
            rB[p] = *(const float4*)(Bm + (long)(k0 + k) * ldb + n0 + n4);
        }
    };
    auto s_store = [&](int buf) {
#pragma unroll
        for (int p = 0; p < 4; p++) {
            int idx = tid + p * 256;
            int m = idx >> 4, k4 = (idx & 15) << 2;
            split_store(smem + S_AB(buf, 0), smem + S_AB(buf, 1),
                        (uint32_t)(m * S_APITCH + k4) * 2, rA[p]);
        }
#pragma unroll
        for (int p = 0; p < 8; p++) {
            int idx = tid + p * 256;
            int k = idx >> 5, n4 = (idx & 31) << 2;
            split_store(smem + S_BB(buf, 0), smem + S_BB(buf, 1),
                        (uint32_t)(k * S_BPITCH + n4) * 2, rB[p]);
        }
    };

    g_load(0);
    s_store(0);
    __syncthreads();

    for (int kc = 0; kc < 4; kc++) {
        const int cur = kc & 1;
        if (kc < 3) g_load(kc + 1);

        const uint32_t Ah = sb + S_AB(cur, 0), Al = sb + S_AB(cur, 1);
        const uint32_t Bh = sb + S_BB(cur, 0), Bl = sb + S_BB(cur, 1);
#pragma unroll
        for (int ks = 0; ks < 4; ks++) {
            uint32_t ah[2][4], al[2][4], bh[2][4], bl[2][4];
#pragma unroll
            for (int mf = 0; mf < 2; mf++) {
                LDSM(ah[mf], Ah + aoff[mf] + ks * 32);
                LDSM(al[mf], Al + aoff[mf] + ks * 32);
            }
#pragma unroll
            for (int q = 0; q < 2; q++) {
                LDSM_T(bh[q], Bh + boff[q] + ks * (16 * S_BPITCH * 2));
                LDSM_T(bl[q], Bl + boff[q] + ks * (16 * S_BPITCH * 2));
            }
#pragma unroll
            for (int mf = 0; mf < 2; mf++)
#pragma unroll
                for (int nf = 0; nf < 4; nf++) {
                    int q = nf >> 1, h = nf & 1;
                    MMA_BF16(acc[mf][nf], ah[mf], bh[q][h], bh[q][h + 2]);
                    MMA_BF16(acc[mf][nf], ah[mf], bl[q][h], bl[q][h + 2]);
                    MMA_BF16(acc[mf][nf], al[mf], bh[q][h], bh[q][h + 2]);
                }
        }
        if (kc < 3) s_store(1 - cur);
        __syncthreads();
    }

#pragma unroll
    for (int mf = 0; mf < 2; mf++) {
        int mrow = warp_m * 32 + mf * 16 + (lane >> 2);
#pragma unroll
        for (int nf = 0; nf < 4; nf++) {
            int n = warp_n * 32 + nf * 8 + (lane & 3) * 2;
            float2 bb = *(const float2*)(bias + n0 + n);
            float2 s0 = make_float2(acc[mf][nf][0] + bb.x, acc[mf][nf][1] + bb.y);
            float2 s1 = make_float2(acc[mf][nf][2] + bb.x, acc[mf][nf][3] + bb.y);
            if (RES) {
                if (m0 + mrow < M) {
                    float2 r = *(const float2*)(Rm + (long)(m0 + mrow) * ldc + n0 + n);
                    s0.x += r.x; s0.y += r.y;
                }
                if (m0 + mrow + 8 < M) {
                    float2 r = *(const float2*)(Rm + (long)(m0 + mrow + 8) * ldc + n0 + n);
                    s1.x += r.x; s1.y += r.y;
                }
            }
            if (m0 + mrow < M)
                *(float2*)(C + (long)(m0 + mrow) * ldc + n0 + n) = s0;
            if (m0 + mrow + 8 < M)
                *(float2*)(C + (long)(m0 + mrow + 8) * ldc + n0 + n) = s1;
        }
    }
}

template <bool RES>
__global__ void __launch_bounds__(256) gemm_small(
    const float* __restrict__ A, const float* __restrict__ Bm,
    const float* __restrict__ bias, const float* __restrict__ Rm,
    float* __restrict__ C, int M, int ldb, int ldc)
{
    extern __shared__ char smem[];
    gemm_core<RES>(A, Bm, bias, Rm, C, M, blockIdx.x * 128, blockIdx.y * 64,
                   ldb, ldc, smem);
}

// Combined projection: bx<2 -> q = query@Wq+bq (cols bx*128); bx==2 -> oa = query@Wf+bf
__global__ void __launch_bounds__(256) proj_kernel(
    const float* __restrict__ query, const float* __restrict__ Wq,
    const float* __restrict__ bq)
{
    extern __shared__ char smem[];
    if (blockIdx.x < 2) {
        gemm_core<false>(query, Wq, bq, nullptr, g_q, BB * NQ,
                         blockIdx.x * 128, blockIdx.y * 64, DD, DD, smem);
    } else {
        gemm_core<false>(query, g_wf, g_bf, nullptr, g_oa, BB * NQ,
                         0, blockIdx.y * 64, 128, 128, smem);
    }
}

// ---------------- Bezier + bilinear sampling + softmax + weighted sum ----------------
__global__ __launch_bounds__(256) void sample_kernel(
    const float* __restrict__ ctrl, const float* __restrict__ pc)
{
    __shared__ float s_ctrl[8];
    __shared__ float s_off[64];
    __shared__ float s_aw[32];
    __shared__ int   s_idx[320][4];
    __shared__ float s_w[320][4];

    const int bn = blockIdx.x;
    const int b = bn / NQ;
    const int tid = threadIdx.x;

    if (tid < 8)  s_ctrl[tid] = ctrl[(long)bn * 8 + tid];
    else if (tid >= 32 && tid < 96) s_off[tid - 32] = g_oa[(long)bn * 128 + (tid - 32)];
    else if (tid >= 96 && tid < 128) s_aw[tid - 96] = g_oa[(long)bn * 128 + 64 + (tid - 96)];
    __syncthreads();

    // softmax over each head's 4 logits (quads of warp 0)
    if (tid < 32) {
        float x = s_aw[tid];
        float m = x;
        m = fmaxf(m, __shfl_xor_sync(0xffffffffu, m, 1));
        m = fmaxf(m, __shfl_xor_sync(0xffffffffu, m, 2));
        float e = expf(x - m);
        float s = e;
        s += __shfl_xor_sync(0xffffffffu, s, 1);
        s += __shfl_xor_sync(0xffffffffu, s, 2);
        s_aw[tid] = e / s;
    }
    __syncthreads();

    const float p0 = pc[0], p1 = pc[1];
    const float invx = 1.f / (pc[3] - p0);
    const float invy = 1.f / (pc[4] - p1);

    for (int it = tid; it < 320; it += 256) {
        const int h = it / 40;
        const int kp = it - h * 40;
        const int k = kp >> 2;
        const int p = kp & 3;

        float t = (float)k * (1.0f / (NK - 1));
        float u = 1.f - t;
        float b0 = u * u * u, b1 = 3.f * u * u * t, b2 = 3.f * u * t * t, b3 = t * t * t;
        float px = b0 * s_ctrl[0] + b1 * s_ctrl[2] + b2 * s_ctrl[4] + b3 * s_ctrl[6];
        float py = b0 * s_ctrl[1] + b1 * s_ctrl[3] + b2 * s_ctrl[5] + b3 * s_ctrl[7];
        float nx = fminf(fmaxf((px - p0) * invx, 0.01f), 0.99f);
        float ny = fminf(fmaxf((py - p1) * invy, 0.01f), 0.99f);

        float gx = (nx + s_off[h * 8 + p * 2 + 0] * (1.f / WW)) * WW - 0.5f;
        float gy = (ny + s_off[h * 8 + p * 2 + 1] * (1.f / HH)) * HH - 0.5f;
        float fx = floorf(gx), fy = floorf(gy);
        float wx = gx - fx, wy = gy - fy;
        int xi = (int)fx, yi = (int)fy;
        float ap = s_aw[h * 4 + p];

#pragma unroll
        for (int c = 0; c < 4; c++) {
            int dx = c & 1, dy = c >> 1;
            int ix = xi + dx, iy = yi + dy;
            bool valid = (ix >= 0) & (ix < WW) & (iy >= 0) & (iy < HH);
            float wgt = valid ? ap * (dx ? wx : 1.f - wx) * (dy ? wy : 1.f - wy) : 0.f;
            int cx = min(max(ix, 0), WW - 1);
            int cy = min(max(iy, 0), HH - 1);
            s_w[it][c] = wgt;
            s_idx[it][c] = cy * WW + cx;
        }
    }
    __syncthreads();

    const int h = tid >> 5, lane = tid & 31;
    const __half* vb = g_vh + (long)b * HWSZ * DD + h * HDIM + lane;
    float acc = 0.f;
    const int base = h * 40;
#pragma unroll 4
    for (int i = 0; i < 40; i++) {
#pragma unroll
        for (int c = 0; c < 4; c++) {
            float w = s_w[base + i][c];
            int idx = s_idx[base + i][c];
            acc = fmaf(w, __half2float(vb[(long)idx * DD]), acc);
        }
    }
    g_s[(long)bn * DD + h * HDIM + lane] = acc;
}

// ---------------- launch ----------------
extern "C" void kernel_launch(void* const* d_in, const int* in_sizes, int n_in,
                              void* d_out, int out_size)
{
    const float* query = (const float*)d_in[0];
    const float* ctrl  = (const float*)d_in[1];
    const float* bev   = (const float*)d_in[2];
    const float* pc    = (const float*)d_in[4];
    const float* Wq    = (const float*)d_in[5];
    const float* bq    = (const float*)d_in[6];
    const float* Wv    = (const float*)d_in[7];
    const float* bv    = (const float*)d_in[8];
    const float* Woff  = (const float*)d_in[9];
    const float* boff  = (const float*)d_in[10];
    const float* Wattn = (const float*)d_in[11];
    const float* battn = (const float*)d_in[12];
    const float* Wmo   = (const float*)d_in[13];
    const float* bmo   = (const float*)d_in[14];
    const float* Wo    = (const float*)d_in[15];
    const float* bo    = (const float*)d_in[16];
    float* out = (float*)d_out;

    float *pq, *ps, *pt, *pwoa, *pwf, *pzero;
    cudaGetSymbolAddress((void**)&pq, g_q);
    cudaGetSymbolAddress((void**)&ps, g_s);
    cudaGetSymbolAddress((void**)&pt, g_t);
    cudaGetSymbolAddress((void**)&pwoa, g_woa);
    cudaGetSymbolAddress((void**)&pwf, g_wf);
    cudaGetSymbolAddress((void**)&pzero, g_zero);

    cudaFuncSetAttribute(gemm_v, cudaFuncAttributeMaxDynamicSharedMemorySize, V_SMEM);
    cudaFuncSetAttribute(gemm_small<false>, cudaFuncAttributeMaxDynamicSharedMemorySize, S_SMEM);
    cudaFuncSetAttribute(gemm_small<true>, cudaFuncAttributeMaxDynamicSharedMemorySize, S_SMEM);
    cudaFuncSetAttribute(proj_kernel, cudaFuncAttributeMaxDynamicSharedMemorySize, S_SMEM);

    const int Mq = BB * NQ;                     // 3600
    const dim3 sg_grid(2, (Mq + 63) / 64);      // 2 x 57

    // pack [Woff|Wattn|0] and fuse with Wq
    pack_woa<<<128, 256>>>(Woff, Wattn);
    conv_wv<<<DD, 256>>>(Wv);
    gemm_small<false><<<dim3(1, 4), 256, S_SMEM>>>(Wq, pwoa, pzero, nullptr, pwf,
                                                   DD, 128, 128);
    bias_f_kernel<<<1, 128>>>(bq, boff, battn);

    // q = query@Wq+bq  AND  oa = query@Wf+bf  in one wave
    proj_kernel<<<dim3(3, (Mq + 63) / 64), 256, S_SMEM>>>(query, Wq, bq);

    // v = bev^T @ Wv + bv  (fp16 output)
    gemm_v<<<dim3(HWSZ / 64, BB), 256, V_SMEM>>>(bev, bv);

    // bezier + softmax + bilinear sampling + attention-weighted sum
    sample_kernel<<<BB * NQ, 256>>>(ctrl, pc);

    // t = s @ Wmo + bmo + q
    gemm_small<true><<<sg_grid, 256, S_SMEM>>>(ps, Wmo, bmo, pq, pt, Mq, DD, DD);

    // out = t @ Wo + bo
    gemm_small<false><<<sg_grid, 256, S_SMEM>>>(pt, Wo, bo, nullptr, out, Mq, DD, DD);
}

// round 11
// speedup vs baseline: 1.0194x; 1.0194x over previous
#include <cuda_runtime.h>
#include <cuda_bf16.h>
#include <cuda_fp16.h>
#include <cstdint>
#include <math.h>

// Problem constants (fixed shapes)
#define BB      4
#define NQ      900
#define DD      256
#define CH      256
#define HH      200
#define WW      200
#define HWSZ    40000
#define NHEADS  8
#define HDIM    32
#define NK      10
#define NPTS    4

// ---------------- scratch (device globals; no runtime allocation) ----------------
__device__ float g_q  [BB * NQ * DD];
__device__ __half g_vh[(long)BB * HWSZ * DD];    // projected BEV values (fp16)
__device__ float g_oa [BB * NQ * 128];           // fused offsets(64)+attn logits(32)+pad
__device__ float g_s  [BB * NQ * DD];
__device__ float g_t  [BB * NQ * DD];
__device__ __half g_bhi[DD * CH];                // WvT [n][k] fp16
__device__ float g_woa[DD * 128];                // packed [Woff | Wattn | 0] fp32 [k][n]
__device__ float g_wf [DD * 128];                // Wq @ woa  [k][n]
__device__ float g_bf [128];                     // bq @ woa + [boff|battn|0]
__device__ float g_zero[128];                    // stays zero

// ---------------- helpers ----------------
__device__ __forceinline__ uint32_t smem_u32(const void* p) {
    uint32_t a;
    asm("{ .reg .u64 t; cvta.to.shared.u64 t, %1; cvt.u32.u64 %0, t; }" : "=r"(a) : "l"(p));
    return a;
}
__device__ __forceinline__ uint32_t bf2u(__nv_bfloat16 a, __nv_bfloat16 b) {
    __nv_bfloat162 t(a, b);
    return *reinterpret_cast<uint32_t*>(&t);
}
__device__ __forceinline__ uint32_t h2u(__half a, __half b) {
    __half2 t(a, b);
    return *reinterpret_cast<uint32_t*>(&t);
}

#define LDSM_T(r, addr) \
    asm volatile("ldmatrix.sync.aligned.m8n8.x4.trans.shared.b16 {%0,%1,%2,%3}, [%4];" \
        : "=r"((r)[0]), "=r"((r)[1]), "=r"((r)[2]), "=r"((r)[3]) : "r"(addr))
#define LDSM(r, addr) \
    asm volatile("ldmatrix.sync.aligned.m8n8.x4.shared.b16 {%0,%1,%2,%3}, [%4];" \
        : "=r"((r)[0]), "=r"((r)[1]), "=r"((r)[2]), "=r"((r)[3]) : "r"(addr))
#define MMA_BF16(c, a, b0, b1) \
    asm volatile("mma.sync.aligned.m16n8k16.row.col.f32.bf16.bf16.f32 " \
        "{%0,%1,%2,%3},{%4,%5,%6,%7},{%8,%9},{%0,%1,%2,%3};" \
        : "+f"((c)[0]), "+f"((c)[1]), "+f"((c)[2]), "+f"((c)[3]) \
        : "r"((a)[0]), "r"((a)[1]), "r"((a)[2]), "r"((a)[3]), "r"(b0), "r"(b1))
#define MMA_F16(c, a, b0, b1) \
    asm volatile("mma.sync.aligned.m16n8k16.row.col.f32.f16.f16.f32 " \
        "{%0,%1,%2,%3},{%4,%5,%6,%7},{%8,%9},{%0,%1,%2,%3};" \
        : "+f"((c)[0]), "+f"((c)[1]), "+f"((c)[2]), "+f"((c)[3]) \
        : "r"((a)[0]), "r"((a)[1]), "r"((a)[2]), "r"((a)[3]), "r"(b0), "r"(b1))
#define CP16(dst, src) \
    asm volatile("cp.async.cg.shared.global [%0], [%1], 16;" :: "r"(dst), "l"(src))
#define CP_COMMIT()  asm volatile("cp.async.commit_group;" ::: "memory")
#define CP_WAIT0()   asm volatile("cp.async.wait_group 0;" ::: "memory")

__device__ __forceinline__ void split_store(char* dst_h, char* dst_l, uint32_t off, float4 v) {
    __nv_bfloat16 h0 = __float2bfloat16(v.x), h1 = __float2bfloat16(v.y);
    __nv_bfloat16 h2 = __float2bfloat16(v.z), h3 = __float2bfloat16(v.w);
    __nv_bfloat16 l0 = __float2bfloat16(v.x - __bfloat162float(h0));
    __nv_bfloat16 l1 = __float2bfloat16(v.y - __bfloat162float(h1));
    __nv_bfloat16 l2 = __float2bfloat16(v.z - __bfloat162float(h2));
    __nv_bfloat16 l3 = __float2bfloat16(v.w - __bfloat162float(h3));
    *(uint2*)(dst_h + off) = make_uint2(bf2u(h0, h1), bf2u(h2, h3));
    *(uint2*)(dst_l + off) = make_uint2(bf2u(l0, l1), bf2u(l2, l3));
}

// ---------------- prep: Wv -> WvT fp16 [n][k]  AND  pack [Woff|Wattn|0] ----------------
__global__ __launch_bounds__(256) void prep_kernel(
    const float* __restrict__ Wv,
    const float* __restrict__ Woff, const float* __restrict__ Wattn)
{
    if (blockIdx.x < 256) {
        int idx = blockIdx.x * 256 + threadIdx.x;   // n*256 + k
        int n = idx >> 8, k = idx & 255;
        g_bhi[idx] = __float2half(Wv[k * DD + n]);
    } else {
        int idx = (blockIdx.x - 256) * 256 + threadIdx.x;   // 0..32767
        int k = idx >> 7, n = idx & 127;
        float v = (n < 64) ? Woff[k * 64 + n] : (n < 96 ? Wattn[k * 32 + (n - 64)] : 0.f);
        g_woa[idx] = v;
    }
}

// ---------------- g_bf = bq @ g_woa + [boff|battn|0]  (warp per output n) ----------------
__global__ __launch_bounds__(256) void bias_f_kernel(
    const float* __restrict__ bq, const float* __restrict__ boff,
    const float* __restrict__ battn)
{
    const int lane = threadIdx.x & 31;
    const int n = blockIdx.x * 8 + (threadIdx.x >> 5);   // 0..127
    float s = 0.f;
#pragma unroll
    for (int i = 0; i < 8; i++) {
        int k = lane + i * 32;
        s = fmaf(bq[k], g_woa[k * 128 + n], s);
    }
#pragma unroll
    for (int d = 16; d > 0; d >>= 1)
        s += __shfl_xor_sync(0xffffffffu, s, d);
    if (lane == 0) {
        float b = (n < 64) ? boff[n] : (n < 96 ? battn[n - 64] : 0.f);
        g_bf[n] = s + b;
    }
}

// =====================================================================
// gemm_v: v[b,m,:] = bev^T[b,m,:] @ WvT^T + bv  (HMMA fp16 x fp16, fp32 acc)
// =====================================================================
#define VA_OFF        0                                     // 32768 bytes
#define VB(buf)       (32768 + (buf) * 16384)               // ..65536
#define V_STG         32768                                 // epilogue stage
#define V_SMEM 66560

__global__ void __launch_bounds__(256, 2) gemm_v(
    const float* __restrict__ bev, const float* __restrict__ bias)
{
    extern __shared__ char smem[];
    const uint32_t sb = smem_u32(smem);
    const int tid = threadIdx.x;
    const int lane = tid & 31;
    const int wid = tid >> 5;
    const int warp_m = wid & 1;
    const int warp_n = wid >> 1;
    const int m0 = blockIdx.x * 64;
    const int b = blockIdx.y;

    const float* Ag = bev + (long)b * CH * HWSZ + m0;

    uint32_t b_dst_off[4], b_goff[4];
#pragma unroll
    for (int p = 0; p < 4; p++) {
        int e = tid + p * 256;
        int n = e >> 2, c = e & 3;
        b_dst_off[p] = (uint32_t)(n * 64 + ((c ^ ((n >> 1) & 3)) << 4));
        b_goff[p] = (uint32_t)(n * 256 + c * 8);
    }

#pragma unroll
    for (int p = 0; p < 4; p++)
        CP16(sb + VB(0) + b_dst_off[p], (const void*)(g_bhi + b_goff[p]));
    CP_COMMIT();

#pragma unroll 4
    for (int p = 0; p < 16; p++) {
        int idx = tid + p * 256;
        int k = idx >> 4;
        int m4 = (idx & 15) << 2;
        float4 v = *(const float4*)(Ag + (long)k * HWSZ + m4);
        int c = m4 >> 3;
        uint32_t off = (uint32_t)(k * 128 + ((c ^ (k & 7)) << 4) + ((m4 & 4) << 1));
        *(uint2*)(smem + VA_OFF + off) = make_uint2(
            h2u(__float2half(v.x), __float2half(v.y)),
            h2u(__float2half(v.z), __float2half(v.w)));
    }

    const int tile = lane >> 3;
    const int kl = (lane & 7) + ((tile & 2) << 2);
    uint32_t aoff[2];
#pragma unroll
    for (int mf = 0; mf < 2; mf++) {
        int c = (warp_m * 32 + mf * 16 + ((tile & 1) << 3)) >> 3;
        aoff[mf] = (uint32_t)(kl * 128 + (((c ^ (kl & 7)) & 7) << 4));
    }
    uint32_t boff[4];
#pragma unroll
    for (int q = 0; q < 4; q++) {
        int n = warp_n * 64 + q * 16 + ((tile & 1) << 3) + (lane & 7);
        int c = (tile & 2) >> 1;
        boff[q] = (uint32_t)(n * 64 + ((c ^ ((n >> 1) & 3)) << 4));
    }

    float acc[2][8][4];
#pragma unroll
    for (int i = 0; i < 2; i++)
#pragma unroll
        for (int j = 0; j < 8; j++)
#pragma unroll
            for (int r = 0; r < 4; r++) acc[i][j][r] = 0.f;

    CP_WAIT0();
    __syncthreads();

    for (int kc = 0; kc < 8; kc++) {
        const int cur = kc & 1;
        if (kc < 7) {
            const uint32_t k0 = (uint32_t)((kc + 1) * 32);
#pragma unroll
            for (int p = 0; p < 4; p++)
                CP16(sb + VB(1 - cur) + b_dst_off[p], (const void*)(g_bhi + b_goff[p] + k0));
            CP_COMMIT();
        }

        const uint32_t Bh = sb + VB(cur);
#pragma unroll
        for (int ks = 0; ks < 2; ks++) {
            uint32_t a[2][4];
            const uint32_t akc = (uint32_t)((kc * 32 + ks * 16) * 128);
#pragma unroll
            for (int mf = 0; mf < 2; mf++)
                LDSM_T(a[mf], sb + VA_OFF + akc + aoff[mf]);

            const uint32_t ksx = (uint32_t)(ks << 5);
            uint32_t bh[2][4];
            LDSM(bh[0], Bh + (boff[0] ^ ksx));
#pragma unroll
            for (int q = 0; q < 4; q++) {
                const int bc = q & 1, bn_ = bc ^ 1;
                if (q < 3)
                    LDSM(bh[bn_], Bh + (boff[q + 1] ^ ksx));
#pragma unroll
                for (int h = 0; h < 2; h++) {
                    const int nf = q * 2 + h;
#pragma unroll
                    for (int mf = 0; mf < 2; mf++)
                        MMA_F16(acc[mf][nf], a[mf], bh[bc][h], bh[bc][h + 2]);
                }
            }
        }

        if (kc < 7) CP_WAIT0();
        __syncthreads();
    }

    char* stg = smem + V_STG;
#pragma unroll
    for (int mf = 0; mf < 2; mf++) {
        int mrow = warp_m * 32 + mf * 16 + (lane >> 2);
#pragma unroll
        for (int nf = 0; nf < 8; nf++) {
            int n = warp_n * 64 + nf * 8 + (lane & 3) * 2;
            float2 bb = *(const float2*)(bias + n);
            __half2 v0 = __floats2half2_rn(acc[mf][nf][0] + bb.x, acc[mf][nf][1] + bb.y);
            __half2 v1 = __floats2half2_rn(acc[mf][nf][2] + bb.x, acc[mf][nf][3] + bb.y);
            *(__half2*)(stg + mrow * 528 + n * 2) = v0;
            *(__half2*)(stg + (mrow + 8) * 528 + n * 2) = v1;
        }
    }
    __syncthreads();
    __half* vout = g_vh + ((long)b * HWSZ + m0) * DD;
#pragma unroll
    for (int i = 0; i < 8; i++) {
        int cid = tid + i * 256;
        int r = cid >> 5, c16 = cid & 31;
        *(uint4*)((char*)vout + (long)r * 512 + c16 * 16) =
            *(const uint4*)(stg + r * 528 + c16 * 16);
    }
}

// =====================================================================
// gemm_core: C[m0.., n0..n0+128] = A[M x 256] @ B[256 x ldb] + bias (+R)
// bf16 3-term split, CTA 64 x 128, 8 warps = 2m x 4n.
// =====================================================================
#define S_APITCH 72
#define S_BPITCH 136
#define S_ASZ    (64 * S_APITCH * 2)            // 9216
#define S_BSZ    (64 * S_BPITCH * 2)            // 17408
#define S_AB(buf, hl) (((buf) * 2 + (hl)) * S_ASZ)               // 0..36864
#define S_BB(buf, hl) (36864 + ((buf) * 2 + (hl)) * S_BSZ)       // ..106496
#define S_SMEM 106496

template <bool RES>
__device__ __forceinline__ void gemm_core(
    const float* __restrict__ A, const float* __restrict__ Bm,
    const float* __restrict__ bias, const float* __restrict__ Rm,
    float* __restrict__ C, int M, int n0, int m0, int ldb, int ldc,
    char* smem)
{
    const uint32_t sb = smem_u32(smem);
    const int tid = threadIdx.x;
    const int lane = tid & 31;
    const int wid = tid >> 5;
    const int warp_m = wid & 1;
    const int warp_n = wid >> 1;

    const int tile = lane >> 3;
    uint32_t aoff[2];
#pragma unroll
    for (int mf = 0; mf < 2; mf++) {
        int ml = warp_m * 32 + mf * 16 + ((tile & 1) << 3) + (lane & 7);
        int kcol = (tile & 2) << 2;
        aoff[mf] = (uint32_t)(ml * S_APITCH + kcol) * 2;
    }
    uint32_t boff[2];
#pragma unroll
    for (int q = 0; q < 2; q++) {
        int kr = (lane & 7) + ((tile & 2) << 2);
        int nc = warp_n * 32 + q * 16 + ((tile & 1) << 3);
        boff[q] = (uint32_t)(kr * S_BPITCH + nc) * 2;
    }

    float acc[2][4][4];
#pragma unroll
    for (int i = 0; i < 2; i++)
#pragma unroll
        for (int j = 0; j < 4; j++)
#pragma unroll
            for (int r = 0; r < 4; r++) acc[i][j][r] = 0.f;

    float4 rA[4], rB[8];

    auto g_load = [&](int kc) {
        const int k0 = kc * 64;
#pragma unroll
        for (int p = 0; p < 4; p++) {
            int idx = tid + p * 256;
            int m = idx >> 4, k4 = (idx & 15) << 2;
            rA[p] = (m0 + m < M) ? *(const float4*)(A + (long)(m0 + m) * DD + k0 + k4)
                                 : make_float4(0.f, 0.f, 0.f, 0.f);
        }
#pragma unroll
        for (int p = 0; p < 8; p++) {
            int idx = tid + p * 256;
            int k = idx >> 5, n4 = (idx & 31) << 2;
            rB[p] = *(const float4*)(Bm + (long)(k0 + k) * ldb + n0 + n4);
        }
    };
    auto s_store = [&](int buf) {
#pragma unroll
        for (int p = 0; p < 4; p++) {
            int idx = tid + p * 256;
            int m = idx >> 4, k4 = (idx & 15) << 2;
            split_store(smem + S_AB(buf, 0), smem + S_AB(buf, 1),
                        (uint32_t)(m * S_APITCH + k4) * 2, rA[p]);
        }
#pragma unroll
        for (int p = 0; p < 8; p++) {
            int idx = tid + p * 256;
            int k = idx >> 5, n4 = (idx & 31) << 2;
            split_store(smem + S_BB(buf, 0), smem + S_BB(buf, 1),
                        (uint32_t)(k * S_BPITCH + n4) * 2, rB[p]);
        }
    };

    g_load(0);
    s_store(0);
    __syncthreads();

    for (int kc = 0; kc < 4; kc++) {
        const int cur = kc & 1;
        if (kc < 3) g_load(kc + 1);

        const uint32_t Ah = sb + S_AB(cur, 0), Al = sb + S_AB(cur, 1);
        const uint32_t Bh = sb + S_BB(cur, 0), Bl = sb + S_BB(cur, 1);
#pragma unroll
        for (int ks = 0; ks < 4; ks++) {
            uint32_t ah[2][4], al[2][4], bh[2][4], bl[2][4];
#pragma unroll
            for (int mf = 0; mf < 2; mf++) {
                LDSM(ah[mf], Ah + aoff[mf] + ks * 32);
                LDSM(al[mf], Al + aoff[mf] + ks * 32);
            }
#pragma unroll
            for (int q = 0; q < 2; q++) {
                LDSM_T(bh[q], Bh + boff[q] + ks * (16 * S_BPITCH * 2));
                LDSM_T(bl[q], Bl + boff[q] + ks * (16 * S_BPITCH * 2));
            }
#pragma unroll
            for (int mf = 0; mf < 2; mf++)
#pragma unroll
                for (int nf = 0; nf < 4; nf++) {
                    int q = nf >> 1, h = nf & 1;
                    MMA_BF16(acc[mf][nf], ah[mf], bh[q][h], bh[q][h + 2]);
                    MMA_BF16(acc[mf][nf], ah[mf], bl[q][h], bl[q][h + 2]);
                    MMA_BF16(acc[mf][nf], al[mf], bh[q][h], bh[q][h + 2]);
                }
        }
        if (kc < 3) s_store(1 - cur);
        __syncthreads();
    }

#pragma unroll
    for (int mf = 0; mf < 2; mf++) {
        int mrow = warp_m * 32 + mf * 16 + (lane >> 2);
#pragma unroll
        for (int nf = 0; nf < 4; nf++) {
            int n = warp_n * 32 + nf * 8 + (lane & 3) * 2;
            float2 bb = *(const float2*)(bias + n0 + n);
            float2 s0 = make_float2(acc[mf][nf][0] + bb.x, acc[mf][nf][1] + bb.y);
            float2 s1 = make_float2(acc[mf][nf][2] + bb.x, acc[mf][nf][3] + bb.y);
            if (RES) {
                if (m0 + mrow < M) {
                    float2 r = *(const float2*)(Rm + (long)(m0 + mrow) * ldc + n0 + n);
                    s0.x += r.x; s0.y += r.y;
                }
                if (m0 + mrow + 8 < M) {
                    float2 r = *(const float2*)(Rm + (long)(m0 + mrow + 8) * ldc + n0 + n);
                    s1.x += r.x; s1.y += r.y;
                }
            }
            if (m0 + mrow < M)
                *(float2*)(C + (long)(m0 + mrow) * ldc + n0 + n) = s0;
            if (m0 + mrow + 8 < M)
                *(float2*)(C + (long)(m0 + mrow + 8) * ldc + n0 + n) = s1;
        }
    }
}

template <bool RES>
__global__ void __launch_bounds__(256) gemm_small(
    const float* __restrict__ A, const float* __restrict__ Bm,
    const float* __restrict__ bias, const float* __restrict__ Rm,
    float* __restrict__ C, int M, int ldb, int ldc)
{
    extern __shared__ char smem[];
    gemm_core<RES>(A, Bm, bias, Rm, C, M, blockIdx.x * 128, blockIdx.y * 64,
                   ldb, ldc, smem);
}

// Combined projection: bx<2 -> q = query@Wq+bq (cols bx*128); bx==2 -> oa = query@Wf+bf
__global__ void __launch_bounds__(256) proj_kernel(
    const float* __restrict__ query, const float* __restrict__ Wq,
    const float* __restrict__ bq)
{
    extern __shared__ char smem[];
    if (blockIdx.x < 2) {
        gemm_core<false>(query, Wq, bq, nullptr, g_q, BB * NQ,
                         blockIdx.x * 128, blockIdx.y * 64, DD, DD, smem);
    } else {
        gemm_core<false>(query, g_wf, g_bf, nullptr, g_oa, BB * NQ,
                         0, blockIdx.y * 64, 128, 128, smem);
    }
}

// ---------------- Bezier + bilinear sampling + softmax + weighted sum ----------------
__global__ __launch_bounds__(256) void sample_kernel(
    const float* __restrict__ ctrl, const float* __restrict__ pc)
{
    __shared__ float s_ctrl[8];
    __shared__ float s_off[64];
    __shared__ float s_aw[32];
    __shared__ int   s_idx[320][4];
    __shared__ float s_w[320][4];

    const int bn = blockIdx.x;
    const int b = bn / NQ;
    const int tid = threadIdx.x;

    if (tid < 8)  s_ctrl[tid] = ctrl[(long)bn * 8 + tid];
    else if (tid >= 32 && tid < 96) s_off[tid - 32] = g_oa[(long)bn * 128 + (tid - 32)];
    else if (tid >= 96 && tid < 128) s_aw[tid - 96] = g_oa[(long)bn * 128 + 64 + (tid - 96)];
    __syncthreads();

    // softmax over each head's 4 logits (quads of warp 0)
    if (tid < 32) {
        float x = s_aw[tid];
        float m = x;
        m = fmaxf(m, __shfl_xor_sync(0xffffffffu, m, 1));
        m = fmaxf(m, __shfl_xor_sync(0xffffffffu, m, 2));
        float e = expf(x - m);
        float s = e;
        s += __shfl_xor_sync(0xffffffffu, s, 1);
        s += __shfl_xor_sync(0xffffffffu, s, 2);
        s_aw[tid] = e / s;
    }
    __syncthreads();

    const float p0 = pc[0], p1 = pc[1];
    const float invx = 1.f / (pc[3] - p0);
    const float invy = 1.f / (pc[4] - p1);

    for (int it = tid; it < 320; it += 256) {
        const int h = it / 40;
        const int kp = it - h * 40;
        const int k = kp >> 2;
        const int p = kp & 3;

        float t = (float)k * (1.0f / (NK - 1));
        float u = 1.f - t;
        float b0 = u * u * u, b1 = 3.f * u * u * t, b2 = 3.f * u * t * t, b3 = t * t * t;
        float px = b0 * s_ctrl[0] + b1 * s_ctrl[2] + b2 * s_ctrl[4] + b3 * s_ctrl[6];
        float py = b0 * s_ctrl[1] + b1 * s_ctrl[3] + b2 * s_ctrl[5] + b3 * s_ctrl[7];
        float nx = fminf(fmaxf((px - p0) * invx, 0.01f), 0.99f);
        float ny = fminf(fmaxf((py - p1) * invy, 0.01f), 0.99f);

        float gx = (nx + s_off[h * 8 + p * 2 + 0] * (1.f / WW)) * WW - 0.5f;
        float gy = (ny + s_off[h * 8 + p * 2 + 1] * (1.f / HH)) * HH - 0.5f;
        float fx = floorf(gx), fy = floorf(gy);
        float wx = gx - fx, wy = gy - fy;
        int xi = (int)fx, yi = (int)fy;
        float ap = s_aw[h * 4 + p];

#pragma unroll
        for (int c = 0; c < 4; c++) {
            int dx = c & 1, dy = c >> 1;
            int ix = xi + dx, iy = yi + dy;
            bool valid = (ix >= 0) & (ix < WW) & (iy >= 0) & (iy < HH);
            float wgt = valid ? ap * (dx ? wx : 1.f - wx) * (dy ? wy : 1.f - wy) : 0.f;
            int cx = min(max(ix, 0), WW - 1);
            int cy = min(max(iy, 0), HH - 1);
            s_w[it][c] = wgt;
            s_idx[it][c] = cy * WW + cx;
        }
    }
    __syncthreads();

    const int h = tid >> 5, lane = tid & 31;
    const __half* vb = g_vh + (long)b * HWSZ * DD + h * HDIM + lane;
    float acc = 0.f;
    const int base = h * 40;
#pragma unroll 4
    for (int i = 0; i < 40; i++) {
#pragma unroll
        for (int c = 0; c < 4; c++) {
            float w = s_w[base + i][c];
            int idx = s_idx[base + i][c];
            acc = fmaf(w, __half2float(vb[(long)idx * DD]), acc);
        }
    }
    g_s[(long)bn * DD + h * HDIM + lane] = acc;
}

// ---------------- launch ----------------
extern "C" void kernel_launch(void* const* d_in, const int* in_sizes, int n_in,
                              void* d_out, int out_size)
{
    const float* query = (const float*)d_in[0];
    const float* ctrl  = (const float*)d_in[1];
    const float* bev   = (const float*)d_in[2];
    const float* pc    = (const float*)d_in[4];
    const float* Wq    = (const float*)d_in[5];
    const float* bq    = (const float*)d_in[6];
    const float* Wv    = (const float*)d_in[7];
    const float* bv    = (const float*)d_in[8];
    const float* Woff  = (const float*)d_in[9];
    const float* boff  = (const float*)d_in[10];
    const float* Wattn = (const float*)d_in[11];
    const float* battn = (const float*)d_in[12];
    const float* Wmo   = (const float*)d_in[13];
    const float* bmo   = (const float*)d_in[14];
    const float* Wo    = (const float*)d_in[15];
    const float* bo    = (const float*)d_in[16];
    float* out = (float*)d_out;

    float *pq, *ps, *pt, *pwoa, *pwf, *pzero;
    cudaGetSymbolAddress((void**)&pq, g_q);
    cudaGetSymbolAddress((void**)&ps, g_s);
    cudaGetSymbolAddress((void**)&pt, g_t);
    cudaGetSymbolAddress((void**)&pwoa, g_woa);
    cudaGetSymbolAddress((void**)&pwf, g_wf);
    cudaGetSymbolAddress((void**)&pzero, g_zero);

    cudaFuncSetAttribute(gemm_v, cudaFuncAttributeMaxDynamicSharedMemorySize, V_SMEM);
    cudaFuncSetAttribute(gemm_small<false>, cudaFuncAttributeMaxDynamicSharedMemorySize, S_SMEM);
    cudaFuncSetAttribute(gemm_small<true>, cudaFuncAttributeMaxDynamicSharedMemorySize, S_SMEM);
    cudaFuncSetAttribute(proj_kernel, cudaFuncAttributeMaxDynamicSharedMemorySize, S_SMEM);

    const int Mq = BB * NQ;                     // 3600
    const dim3 sg_grid(2, (Mq + 63) / 64);      // 2 x 57

    // Wv conversion + [Woff|Wattn|0] packing in one wave
    prep_kernel<<<384, 256>>>(Wv, Woff, Wattn);
    // fused weight: wf = Wq @ woa
    gemm_small<false><<<dim3(1, 4), 256, S_SMEM>>>(Wq, pwoa, pzero, nullptr, pwf,
                                                   DD, 128, 128);
    // fused bias: bf = bq @ woa + [boff|battn|0]  (warp per output)
    bias_f_kernel<<<16, 256>>>(bq, boff, battn);

    // q = query@Wq+bq  AND  oa = query@Wf+bf  in one wave
    proj_kernel<<<dim3(3, (Mq + 63) / 64), 256, S_SMEM>>>(query, Wq, bq);

    // v = bev^T @ Wv + bv  (fp16 output)
    gemm_v<<<dim3(HWSZ / 64, BB), 256, V_SMEM>>>(bev, bv);

    // bezier + softmax + bilinear sampling + attention-weighted sum
    sample_kernel<<<BB * NQ, 256>>>(ctrl, pc);

    // t = s @ Wmo + bmo + q
    gemm_small<true><<<sg_grid, 256, S_SMEM>>>(ps, Wmo, bmo, pq, pt, Mq, DD, DD);

    // out = t @ Wo + bo
    gemm_small<false><<<sg_grid, 256, S_SMEM>>>(pt, Wo, bo, nullptr, out, Mq, DD, DD);
}

// round 12
// speedup vs baseline: 1.1024x; 1.0813x over previous
#include <cuda_runtime.h>
#include <cuda_bf16.h>
#include <cuda_fp16.h>
#include <cstdint>
#include <math.h>

// Problem constants (fixed shapes)
#define BB      4
#define NQ      900
#define DD      256
#define CH      256
#define HH      200
#define WW      200
#define HWSZ    40000
#define NHEADS  8
#define HDIM    32
#define NK      10
#define NPTS    4

// ---------------- scratch (device globals; no runtime allocation) ----------------
__device__ __half g_vh[(long)BB * HWSZ * DD];    // projected BEV values (fp16)
__device__ float g_oa [BB * NQ * 128];           // fused offsets(64)+attn logits(32)+pad
__device__ float g_qo [BB * NQ * DD];            // query@W3 + b2 (residual-through-Wo)
__device__ float g_s  [BB * NQ * DD];
__device__ __half g_bhi[DD * CH];                // WvT [n][k] fp16
__device__ float g_woa[DD * 128];                // packed [Woff | Wattn | 0] fp32 [k][n]
__device__ float g_wf [DD * 128];                // Wq @ woa  [k][n]
__device__ float g_w2 [DD * DD];                 // Wmo @ Wo
__device__ float g_w3 [DD * DD];                 // Wq @ Wo
__device__ float g_bf [128];                     // bq @ woa + [boff|battn|0]
__device__ float g_b2 [DD];                      // (bq+bmo) @ Wo + bo
__device__ float g_zero[DD];                     // stays zero

// ---------------- helpers ----------------
__device__ __forceinline__ uint32_t smem_u32(const void* p) {
    uint32_t a;
    asm("{ .reg .u64 t; cvta.to.shared.u64 t, %1; cvt.u32.u64 %0, t; }" : "=r"(a) : "l"(p));
    return a;
}
__device__ __forceinline__ uint32_t bf2u(__nv_bfloat16 a, __nv_bfloat16 b) {
    __nv_bfloat162 t(a, b);
    return *reinterpret_cast<uint32_t*>(&t);
}
__device__ __forceinline__ uint32_t h2u(__half a, __half b) {
    __half2 t(a, b);
    return *reinterpret_cast<uint32_t*>(&t);
}

#define LDSM_T(r, addr) \
    asm volatile("ldmatrix.sync.aligned.m8n8.x4.trans.shared.b16 {%0,%1,%2,%3}, [%4];" \
        : "=r"((r)[0]), "=r"((r)[1]), "=r"((r)[2]), "=r"((r)[3]) : "r"(addr))
#define LDSM(r, addr) \
    asm volatile("ldmatrix.sync.aligned.m8n8.x4.shared.b16 {%0,%1,%2,%3}, [%4];" \
        : "=r"((r)[0]), "=r"((r)[1]), "=r"((r)[2]), "=r"((r)[3]) : "r"(addr))
#define MMA_BF16(c, a, b0, b1) \
    asm volatile("mma.sync.aligned.m16n8k16.row.col.f32.bf16.bf16.f32 " \
        "{%0,%1,%2,%3},{%4,%5,%6,%7},{%8,%9},{%0,%1,%2,%3};" \
        : "+f"((c)[0]), "+f"((c)[1]), "+f"((c)[2]), "+f"((c)[3]) \
        : "r"((a)[0]), "r"((a)[1]), "r"((a)[2]), "r"((a)[3]), "r"(b0), "r"(b1))
#define MMA_F16(c, a, b0, b1) \
    asm volatile("mma.sync.aligned.m16n8k16.row.col.f32.f16.f16.f32 " \
        "{%0,%1,%2,%3},{%4,%5,%6,%7},{%8,%9},{%0,%1,%2,%3};" \
        : "+f"((c)[0]), "+f"((c)[1]), "+f"((c)[2]), "+f"((c)[3]) \
        : "r"((a)[0]), "r"((a)[1]), "r"((a)[2]), "r"((a)[3]), "r"(b0), "r"(b1))
#define CP16(dst, src) \
    asm volatile("cp.async.cg.shared.global [%0], [%1], 16;" :: "r"(dst), "l"(src))
#define CP_COMMIT()  asm volatile("cp.async.commit_group;" ::: "memory")
#define CP_WAIT0()   asm volatile("cp.async.wait_group 0;" ::: "memory")

__device__ __forceinline__ void split_store(char* dst_h, char* dst_l, uint32_t off, float4 v) {
    __nv_bfloat16 h0 = __float2bfloat16(v.x), h1 = __float2bfloat16(v.y);
    __nv_bfloat16 h2 = __float2bfloat16(v.z), h3 = __float2bfloat16(v.w);
    __nv_bfloat16 l0 = __float2bfloat16(v.x - __bfloat162float(h0));
    __nv_bfloat16 l1 = __float2bfloat16(v.y - __bfloat162float(h1));
    __nv_bfloat16 l2 = __float2bfloat16(v.z - __bfloat162float(h2));
    __nv_bfloat16 l3 = __float2bfloat16(v.w - __bfloat162float(h3));
    *(uint2*)(dst_h + off) = make_uint2(bf2u(h0, h1), bf2u(h2, h3));
    *(uint2*)(dst_l + off) = make_uint2(bf2u(l0, l1), bf2u(l2, l3));
}

// ---------------- prep: Wv -> WvT fp16 [n][k]  AND  pack [Woff|Wattn|0] ----------------
__global__ __launch_bounds__(256) void prep_kernel(
    const float* __restrict__ Wv,
    const float* __restrict__ Woff, const float* __restrict__ Wattn)
{
    if (blockIdx.x < 256) {
        int idx = blockIdx.x * 256 + threadIdx.x;   // n*256 + k
        int n = idx >> 8, k = idx & 255;
        g_bhi[idx] = __float2half(Wv[k * DD + n]);
    } else {
        int idx = (blockIdx.x - 256) * 256 + threadIdx.x;   // 0..32767
        int k = idx >> 7, n = idx & 127;
        float v = (n < 64) ? Woff[k * 64 + n] : (n < 96 ? Wattn[k * 32 + (n - 64)] : 0.f);
        g_woa[idx] = v;
    }
}

// ---------------- fused biases (warp per output) ----------------
// n<256: g_b2[n] = sum_k (bq+bmo)[k]*Wo[k][n] + bo[n]
// else:  g_bf[n-256] = sum_k bq[k]*woa[k][n-256] + [boff|battn|0]
__global__ __launch_bounds__(256) void bias_kernel(
    const float* __restrict__ bq, const float* __restrict__ bmo,
    const float* __restrict__ bo, const float* __restrict__ boff,
    const float* __restrict__ battn, const float* __restrict__ Wo)
{
    const int lane = threadIdx.x & 31;
    const int n = blockIdx.x * 8 + (threadIdx.x >> 5);   // 0..383
    float s = 0.f;
    if (n < 256) {
#pragma unroll
        for (int i = 0; i < 8; i++) {
            int k = lane + i * 32;
            s = fmaf(bq[k] + bmo[k], Wo[k * DD + n], s);
        }
    } else {
        int nn = n - 256;
#pragma unroll
        for (int i = 0; i < 8; i++) {
            int k = lane + i * 32;
            s = fmaf(bq[k], g_woa[k * 128 + nn], s);
        }
    }
#pragma unroll
    for (int d = 16; d > 0; d >>= 1)
        s += __shfl_xor_sync(0xffffffffu, s, d);
    if (lane == 0) {
        if (n < 256) {
            g_b2[n] = s + bo[n];
        } else {
            int nn = n - 256;
            float b = (nn < 64) ? boff[nn] : (nn < 96 ? battn[nn - 64] : 0.f);
            g_bf[nn] = s + b;
        }
    }
}

// =====================================================================
// gemm_v: v[b,m,:] = bev^T[b,m,:] @ WvT^T + bv  (HMMA fp16 x fp16, fp32 acc)
// =====================================================================
#define VA_OFF        0                                     // 32768 bytes
#define VB(buf)       (32768 + (buf) * 16384)               // ..65536
#define V_STG         32768                                 // epilogue stage
#define V_SMEM 66560

__global__ void __launch_bounds__(256, 2) gemm_v(
    const float* __restrict__ bev, const float* __restrict__ bias)
{
    extern __shared__ char smem[];
    const uint32_t sb = smem_u32(smem);
    const int tid = threadIdx.x;
    const int lane = tid & 31;
    const int wid = tid >> 5;
    const int warp_m = wid & 1;
    const int warp_n = wid >> 1;
    const int m0 = blockIdx.x * 64;
    const int b = blockIdx.y;

    const float* Ag = bev + (long)b * CH * HWSZ + m0;

    uint32_t b_dst_off[4], b_goff[4];
#pragma unroll
    for (int p = 0; p < 4; p++) {
        int e = tid + p * 256;
        int n = e >> 2, c = e & 3;
        b_dst_off[p] = (uint32_t)(n * 64 + ((c ^ ((n >> 1) & 3)) << 4));
        b_goff[p] = (uint32_t)(n * 256 + c * 8);
    }

#pragma unroll
    for (int p = 0; p < 4; p++)
        CP16(sb + VB(0) + b_dst_off[p], (const void*)(g_bhi + b_goff[p]));
    CP_COMMIT();

#pragma unroll 4
    for (int p = 0; p < 16; p++) {
        int idx = tid + p * 256;
        int k = idx >> 4;
        int m4 = (idx & 15) << 2;
        float4 v = *(const float4*)(Ag + (long)k * HWSZ + m4);
        int c = m4 >> 3;
        uint32_t off = (uint32_t)(k * 128 + ((c ^ (k & 7)) << 4) + ((m4 & 4) << 1));
        *(uint2*)(smem + VA_OFF + off) = make_uint2(
            h2u(__float2half(v.x), __float2half(v.y)),
            h2u(__float2half(v.z), __float2half(v.w)));
    }

    const int tile = lane >> 3;
    const int kl = (lane & 7) + ((tile & 2) << 2);
    uint32_t aoff[2];
#pragma unroll
    for (int mf = 0; mf < 2; mf++) {
        int c = (warp_m * 32 + mf * 16 + ((tile & 1) << 3)) >> 3;
        aoff[mf] = (uint32_t)(kl * 128 + (((c ^ (kl & 7)) & 7) << 4));
    }
    uint32_t boff[4];
#pragma unroll
    for (int q = 0; q < 4; q++) {
        int n = warp_n * 64 + q * 16 + ((tile & 1) << 3) + (lane & 7);
        int c = (tile & 2) >> 1;
        boff[q] = (uint32_t)(n * 64 + ((c ^ ((n >> 1) & 3)) << 4));
    }

    float acc[2][8][4];
#pragma unroll
    for (int i = 0; i < 2; i++)
#pragma unroll
        for (int j = 0; j < 8; j++)
#pragma unroll
            for (int r = 0; r < 4; r++) acc[i][j][r] = 0.f;

    CP_WAIT0();
    __syncthreads();

    for (int kc = 0; kc < 8; kc++) {
        const int cur = kc & 1;
        if (kc < 7) {
            const uint32_t k0 = (uint32_t)((kc + 1) * 32);
#pragma unroll
            for (int p = 0; p < 4; p++)
                CP16(sb + VB(1 - cur) + b_dst_off[p], (const void*)(g_bhi + b_goff[p] + k0));
            CP_COMMIT();
        }

        const uint32_t Bh = sb + VB(cur);
#pragma unroll
        for (int ks = 0; ks < 2; ks++) {
            uint32_t a[2][4];
            const uint32_t akc = (uint32_t)((kc * 32 + ks * 16) * 128);
#pragma unroll
            for (int mf = 0; mf < 2; mf++)
                LDSM_T(a[mf], sb + VA_OFF + akc + aoff[mf]);

            const uint32_t ksx = (uint32_t)(ks << 5);
            uint32_t bh[2][4];
            LDSM(bh[0], Bh + (boff[0] ^ ksx));
#pragma unroll
            for (int q = 0; q < 4; q++) {
                const int bc = q & 1, bn_ = bc ^ 1;
                if (q < 3)
                    LDSM(bh[bn_], Bh + (boff[q + 1] ^ ksx));
#pragma unroll
                for (int h = 0; h < 2; h++) {
                    const int nf = q * 2 + h;
#pragma unroll
                    for (int mf = 0; mf < 2; mf++)
                        MMA_F16(acc[mf][nf], a[mf], bh[bc][h], bh[bc][h + 2]);
                }
            }
        }

        if (kc < 7) CP_WAIT0();
        __syncthreads();
    }

    char* stg = smem + V_STG;
#pragma unroll
    for (int mf = 0; mf < 2; mf++) {
        int mrow = warp_m * 32 + mf * 16 + (lane >> 2);
#pragma unroll
        for (int nf = 0; nf < 8; nf++) {
            int n = warp_n * 64 + nf * 8 + (lane & 3) * 2;
            float2 bb = *(const float2*)(bias + n);
            __half2 v0 = __floats2half2_rn(acc[mf][nf][0] + bb.x, acc[mf][nf][1] + bb.y);
            __half2 v1 = __floats2half2_rn(acc[mf][nf][2] + bb.x, acc[mf][nf][3] + bb.y);
            *(__half2*)(stg + mrow * 528 + n * 2) = v0;
            *(__half2*)(stg + (mrow + 8) * 528 + n * 2) = v1;
        }
    }
    __syncthreads();
    __half* vout = g_vh + ((long)b * HWSZ + m0) * DD;
#pragma unroll
    for (int i = 0; i < 8; i++) {
        int cid = tid + i * 256;
        int r = cid >> 5, c16 = cid & 31;
        *(uint4*)((char*)vout + (long)r * 512 + c16 * 16) =
            *(const uint4*)(stg + r * 528 + c16 * 16);
    }
}

// =====================================================================
// gemm_core: C[m0.., n0..n0+128] = A[M x 256] @ B[256 x ldb] + bias (+R)
// bf16 3-term split, CTA 64 x 128, 8 warps = 2m x 4n.
// =====================================================================
#define S_APITCH 72
#define S_BPITCH 136
#define S_ASZ    (64 * S_APITCH * 2)            // 9216
#define S_BSZ    (64 * S_BPITCH * 2)            // 17408
#define S_AB(buf, hl) (((buf) * 2 + (hl)) * S_ASZ)               // 0..36864
#define S_BB(buf, hl) (36864 + ((buf) * 2 + (hl)) * S_BSZ)       // ..106496
#define S_SMEM 106496

template <bool RES>
__device__ __forceinline__ void gemm_core(
    const float* __restrict__ A, const float* __restrict__ Bm,
    const float* __restrict__ bias, const float* __restrict__ Rm,
    float* __restrict__ C, int M, int n0, int m0, int ldb, int ldc,
    char* smem)
{
    const uint32_t sb = smem_u32(smem);
    const int tid = threadIdx.x;
    const int lane = tid & 31;
    const int wid = tid >> 5;
    const int warp_m = wid & 1;
    const int warp_n = wid >> 1;

    const int tile = lane >> 3;
    uint32_t aoff[2];
#pragma unroll
    for (int mf = 0; mf < 2; mf++) {
        int ml = warp_m * 32 + mf * 16 + ((tile & 1) << 3) + (lane & 7);
        int kcol = (tile & 2) << 2;
        aoff[mf] = (uint32_t)(ml * S_APITCH + kcol) * 2;
    }
    uint32_t boff[2];
#pragma unroll
    for (int q = 0; q < 2; q++) {
        int kr = (lane & 7) + ((tile & 2) << 2);
        int nc = warp_n * 32 + q * 16 + ((tile & 1) << 3);
        boff[q] = (uint32_t)(kr * S_BPITCH + nc) * 2;
    }

    float acc[2][4][4];
#pragma unroll
    for (int i = 0; i < 2; i++)
#pragma unroll
        for (int j = 0; j < 4; j++)
#pragma unroll
            for (int r = 0; r < 4; r++) acc[i][j][r] = 0.f;

    float4 rA[4], rB[8];

    auto g_load = [&](int kc) {
        const int k0 = kc * 64;
#pragma unroll
        for (int p = 0; p < 4; p++) {
            int idx = tid + p * 256;
            int m = idx >> 4, k4 = (idx & 15) << 2;
            rA[p] = (m0 + m < M) ? *(const float4*)(A + (long)(m0 + m) * DD + k0 + k4)
                                 : make_float4(0.f, 0.f, 0.f, 0.f);
        }
#pragma unroll
        for (int p = 0; p < 8; p++) {
            int idx = tid + p * 256;
            int k = idx >> 5, n4 = (idx & 31) << 2;
            rB[p] = *(const float4*)(Bm + (long)(k0 + k) * ldb + n0 + n4);
        }
    };
    auto s_store = [&](int buf) {
#pragma unroll
        for (int p = 0; p < 4; p++) {
            int idx = tid + p * 256;
            int m = idx >> 4, k4 = (idx & 15) << 2;
            split_store(smem + S_AB(buf, 0), smem + S_AB(buf, 1),
                        (uint32_t)(m * S_APITCH + k4) * 2, rA[p]);
        }
#pragma unroll
        for (int p = 0; p < 8; p++) {
            int idx = tid + p * 256;
            int k = idx >> 5, n4 = (idx & 31) << 2;
            split_store(smem + S_BB(buf, 0), smem + S_BB(buf, 1),
                        (uint32_t)(k * S_BPITCH + n4) * 2, rB[p]);
        }
    };

    g_load(0);
    s_store(0);
    __syncthreads();

    for (int kc = 0; kc < 4; kc++) {
        const int cur = kc & 1;
        if (kc < 3) g_load(kc + 1);

        const uint32_t Ah = sb + S_AB(cur, 0), Al = sb + S_AB(cur, 1);
        const uint32_t Bh = sb + S_BB(cur, 0), Bl = sb + S_BB(cur, 1);
#pragma unroll
        for (int ks = 0; ks < 4; ks++) {
            uint32_t ah[2][4], al[2][4], bh[2][4], bl[2][4];
#pragma unroll
            for (int mf = 0; mf < 2; mf++) {
                LDSM(ah[mf], Ah + aoff[mf] + ks * 32);
                LDSM(al[mf], Al + aoff[mf] + ks * 32);
            }
#pragma unroll
            for (int q = 0; q < 2; q++) {
                LDSM_T(bh[q], Bh + boff[q] + ks * (16 * S_BPITCH * 2));
                LDSM_T(bl[q], Bl + boff[q] + ks * (16 * S_BPITCH * 2));
            }
#pragma unroll
            for (int mf = 0; mf < 2; mf++)
#pragma unroll
                for (int nf = 0; nf < 4; nf++) {
                    int q = nf >> 1, h = nf & 1;
                    MMA_BF16(acc[mf][nf], ah[mf], bh[q][h], bh[q][h + 2]);
                    MMA_BF16(acc[mf][nf], ah[mf], bl[q][h], bl[q][h + 2]);
                    MMA_BF16(acc[mf][nf], al[mf], bh[q][h], bh[q][h + 2]);
                }
        }
        if (kc < 3) s_store(1 - cur);
        __syncthreads();
    }

#pragma unroll
    for (int mf = 0; mf < 2; mf++) {
        int mrow = warp_m * 32 + mf * 16 + (lane >> 2);
#pragma unroll
        for (int nf = 0; nf < 4; nf++) {
            int n = warp_n * 32 + nf * 8 + (lane & 3) * 2;
            float2 bb = *(const float2*)(bias + n0 + n);
            float2 s0 = make_float2(acc[mf][nf][0] + bb.x, acc[mf][nf][1] + bb.y);
            float2 s1 = make_float2(acc[mf][nf][2] + bb.x, acc[mf][nf][3] + bb.y);
            if (RES) {
                if (m0 + mrow < M) {
                    float2 r = *(const float2*)(Rm + (long)(m0 + mrow) * ldc + n0 + n);
                    s0.x += r.x; s0.y += r.y;
                }
                if (m0 + mrow + 8 < M) {
                    float2 r = *(const float2*)(Rm + (long)(m0 + mrow + 8) * ldc + n0 + n);
                    s1.x += r.x; s1.y += r.y;
                }
            }
            if (m0 + mrow < M)
                *(float2*)(C + (long)(m0 + mrow) * ldc + n0 + n) = s0;
            if (m0 + mrow + 8 < M)
                *(float2*)(C + (long)(m0 + mrow + 8) * ldc + n0 + n) = s1;
        }
    }
}

template <bool RES>
__global__ void __launch_bounds__(256) gemm_small(
    const float* __restrict__ A, const float* __restrict__ Bm,
    const float* __restrict__ bias, const float* __restrict__ Rm,
    float* __restrict__ C, int M, int ldb, int ldc)
{
    extern __shared__ char smem[];
    gemm_core<RES>(A, Bm, bias, Rm, C, M, blockIdx.x * 128, blockIdx.y * 64,
                   ldb, ldc, smem);
}

// prep gemms in one wave: W2 = Wmo@Wo (blocks 0-7), W3 = Wq@Wo (8-15), Wf = Wq@woa (16-19)
__global__ void __launch_bounds__(256) prep_gemm(
    const float* __restrict__ Wmo, const float* __restrict__ Wq,
    const float* __restrict__ Wo)
{
    extern __shared__ char smem[];
    int bx = blockIdx.x;
    if (bx < 8) {
        gemm_core<false>(Wmo, Wo, g_zero, nullptr, g_w2, DD,
                         (bx & 1) * 128, (bx >> 1) * 64, DD, DD, smem);
    } else if (bx < 16) {
        bx -= 8;
        gemm_core<false>(Wq, Wo, g_zero, nullptr, g_w3, DD,
                         (bx & 1) * 128, (bx >> 1) * 64, DD, DD, smem);
    } else {
        bx -= 16;
        gemm_core<false>(Wq, g_woa, g_zero, nullptr, g_wf, DD,
                         0, bx * 64, 128, 128, smem);
    }
}

// Combined projection: bx<2 -> qo = query@W3 + b2 (cols bx*128); bx==2 -> oa = query@Wf + bf
__global__ void __launch_bounds__(256) proj_kernel(const float* __restrict__ query)
{
    extern __shared__ char smem[];
    if (blockIdx.x < 2) {
        gemm_core<false>(query, g_w3, g_b2, nullptr, g_qo, BB * NQ,
                         blockIdx.x * 128, blockIdx.y * 64, DD, DD, smem);
    } else {
        gemm_core<false>(query, g_wf, g_bf, nullptr, g_oa, BB * NQ,
                         0, blockIdx.y * 64, 128, 128, smem);
    }
}

// ---------------- Bezier + bilinear sampling + softmax + weighted sum ----------------
__global__ __launch_bounds__(256) void sample_kernel(
    const float* __restrict__ ctrl, const float* __restrict__ pc)
{
    __shared__ float s_ctrl[8];
    __shared__ float s_off[64];
    __shared__ float s_aw[32];
    __shared__ int   s_idx[320][4];
    __shared__ float s_w[320][4];

    const int bn = blockIdx.x;
    const int b = bn / NQ;
    const int tid = threadIdx.x;

    if (tid < 8)  s_ctrl[tid] = ctrl[(long)bn * 8 + tid];
    else if (tid >= 32 && tid < 96) s_off[tid - 32] = g_oa[(long)bn * 128 + (tid - 32)];
    else if (tid >= 96 && tid < 128) s_aw[tid - 96] = g_oa[(long)bn * 128 + 64 + (tid - 96)];
    __syncthreads();

    if (tid < 32) {
        float x = s_aw[tid];
        float m = x;
        m = fmaxf(m, __shfl_xor_sync(0xffffffffu, m, 1));
        m = fmaxf(m, __shfl_xor_sync(0xffffffffu, m, 2));
        float e = expf(x - m);
        float s = e;
        s += __shfl_xor_sync(0xffffffffu, s, 1);
        s += __shfl_xor_sync(0xffffffffu, s, 2);
        s_aw[tid] = e / s;
    }
    __syncthreads();

    const float p0 = pc[0], p1 = pc[1];
    const float invx = 1.f / (pc[3] - p0);
    const float invy = 1.f / (pc[4] - p1);

    for (int it = tid; it < 320; it += 256) {
        const int h = it / 40;
        const int kp = it - h * 40;
        const int k = kp >> 2;
        const int p = kp & 3;

        float t = (float)k * (1.0f / (NK - 1));
        float u = 1.f - t;
        float b0 = u * u * u, b1 = 3.f * u * u * t, b2 = 3.f * u * t * t, b3 = t * t * t;
        float px = b0 * s_ctrl[0] + b1 * s_ctrl[2] + b2 * s_ctrl[4] + b3 * s_ctrl[6];
        float py = b0 * s_ctrl[1] + b1 * s_ctrl[3] + b2 * s_ctrl[5] + b3 * s_ctrl[7];
        float nx = fminf(fmaxf((px - p0) * invx, 0.01f), 0.99f);
        float ny = fminf(fmaxf((py - p1) * invy, 0.01f), 0.99f);

        float gx = (nx + s_off[h * 8 + p * 2 + 0] * (1.f / WW)) * WW - 0.5f;
        float gy = (ny + s_off[h * 8 + p * 2 + 1] * (1.f / HH)) * HH - 0.5f;
        float fx = floorf(gx), fy = floorf(gy);
        float wx = gx - fx, wy = gy - fy;
        int xi = (int)fx, yi = (int)fy;
        float ap = s_aw[h * 4 + p];

#pragma unroll
        for (int c = 0; c < 4; c++) {
            int dx = c & 1, dy = c >> 1;
            int ix = xi + dx, iy = yi + dy;
            bool valid = (ix >= 0) & (ix < WW) & (iy >= 0) & (iy < HH);
            float wgt = valid ? ap * (dx ? wx : 1.f - wx) * (dy ? wy : 1.f - wy) : 0.f;
            int cx = min(max(ix, 0), WW - 1);
            int cy = min(max(iy, 0), HH - 1);
            s_w[it][c] = wgt;
            s_idx[it][c] = cy * WW + cx;
        }
    }
    __syncthreads();

    const int h = tid >> 5, lane = tid & 31;
    const __half* vb = g_vh + (long)b * HWSZ * DD + h * HDIM + lane;
    float acc = 0.f;
    const int base = h * 40;
#pragma unroll 4
    for (int i = 0; i < 40; i++) {
#pragma unroll
        for (int c = 0; c < 4; c++) {
            float w = s_w[base + i][c];
            int idx = s_idx[base + i][c];
            acc = fmaf(w, __half2float(vb[(long)idx * DD]), acc);
        }
    }
    g_s[(long)bn * DD + h * HDIM + lane] = acc;
}

// ---------------- launch ----------------
extern "C" void kernel_launch(void* const* d_in, const int* in_sizes, int n_in,
                              void* d_out, int out_size)
{
    const float* query = (const float*)d_in[0];
    const float* ctrl  = (const float*)d_in[1];
    const float* bev   = (const float*)d_in[2];
    const float* pc    = (const float*)d_in[4];
    const float* Wq    = (const float*)d_in[5];
    const float* bq    = (const float*)d_in[6];
    const float* Wv    = (const float*)d_in[7];
    const float* bv    = (const float*)d_in[8];
    const float* Woff  = (const float*)d_in[9];
    const float* boff  = (const float*)d_in[10];
    const float* Wattn = (const float*)d_in[11];
    const float* battn = (const float*)d_in[12];
    const float* Wmo   = (const float*)d_in[13];
    const float* bmo   = (const float*)d_in[14];
    const float* Wo    = (const float*)d_in[15];
    const float* bo    = (const float*)d_in[16];
    float* out = (float*)d_out;

    float *ps, *pqo, *pw2, *pzero;
    cudaGetSymbolAddress((void**)&ps, g_s);
    cudaGetSymbolAddress((void**)&pqo, g_qo);
    cudaGetSymbolAddress((void**)&pw2, g_w2);
    cudaGetSymbolAddress((void**)&pzero, g_zero);

    cudaFuncSetAttribute(gemm_v, cudaFuncAttributeMaxDynamicSharedMemorySize, V_SMEM);
    cudaFuncSetAttribute(gemm_small<true>, cudaFuncAttributeMaxDynamicSharedMemorySize, S_SMEM);
    cudaFuncSetAttribute(prep_gemm, cudaFuncAttributeMaxDynamicSharedMemorySize, S_SMEM);
    cudaFuncSetAttribute(proj_kernel, cudaFuncAttributeMaxDynamicSharedMemorySize, S_SMEM);

    const int Mq = BB * NQ;                     // 3600

    // Wv conversion + [Woff|Wattn|0] packing in one wave
    prep_kernel<<<384, 256>>>(Wv, Woff, Wattn);
    // W2 = Wmo@Wo, W3 = Wq@Wo, Wf = Wq@woa in one wave
    prep_gemm<<<20, 256, S_SMEM>>>(Wmo, Wq, Wo);
    // b2 = (bq+bmo)@Wo + bo ; bf = bq@woa + [boff|battn|0]
    bias_kernel<<<48, 256>>>(bq, bmo, bo, boff, battn, Wo);

    // qo = query@W3 + b2  AND  oa = query@Wf + bf  in one wave
    proj_kernel<<<dim3(3, (Mq + 63) / 64), 256, S_SMEM>>>(query);

    // v = bev^T @ Wv + bv  (fp16 output)
    gemm_v<<<dim3(HWSZ / 64, BB), 256, V_SMEM>>>(bev, bv);

    // bezier + softmax + bilinear sampling + attention-weighted sum
    sample_kernel<<<BB * NQ, 256>>>(ctrl, pc);

    // out = s@W2 + qo   (single fused tail gemm)
    gemm_small<true><<<dim3(2, (Mq + 63) / 64), 256, S_SMEM>>>(
        ps, pw2, pzero, pqo, out, Mq, DD, DD);
}

// round 14
// speedup vs baseline: 1.1734x; 1.0644x over previous
#include <cuda_runtime.h>
#include <cuda_bf16.h>
#include <cuda_fp16.h>
#include <cstdint>
#include <math.h>

// Problem constants (fixed shapes)
#define BB      4
#define NQ      900
#define DD      256
#define CH      256
#define HH      200
#define WW      200
#define HWSZ    40000
#define NHEADS  8
#define HDIM    32
#define NK      10
#define NPTS    4

// ---------------- scratch (device globals; no runtime allocation) ----------------
__device__ __half g_vh[(long)BB * HWSZ * DD];    // projected BEV values (fp16)
__device__ float g_oa [BB * NQ * 128];           // fused offsets(64)+attn logits(32)+pad
__device__ float g_qo [BB * NQ * DD];            // query@W3 + b2 (residual-through-Wo)
__device__ float g_s  [BB * NQ * DD];
__device__ __half g_bhi[DD * CH];                // WvT [n][k] fp16
__device__ float g_woa[DD * 128];                // packed [Woff | Wattn | 0] fp32 [k][n]
__device__ float g_wf [DD * 128];                // Wq @ woa  [k][n]
__device__ float g_w2 [DD * DD];                 // Wmo @ Wo
__device__ float g_w3 [DD * DD];                 // Wq @ Wo
__device__ float g_bf [128];                     // bq @ woa + [boff|battn|0]
__device__ float g_b2 [DD];                      // (bq+bmo) @ Wo + bo
__device__ float g_zero[DD];                     // stays zero

// ---------------- helpers ----------------
__device__ __forceinline__ uint32_t smem_u32(const void* p) {
    uint32_t a;
    asm("{ .reg .u64 t; cvta.to.shared.u64 t, %1; cvt.u32.u64 %0, t; }" : "=r"(a) : "l"(p));
    return a;
}
__device__ __forceinline__ uint32_t bf2u(__nv_bfloat16 a, __nv_bfloat16 b) {
    __nv_bfloat162 t(a, b);
    return *reinterpret_cast<uint32_t*>(&t);
}
__device__ __forceinline__ uint32_t h2u(__half a, __half b) {
    __half2 t(a, b);
    return *reinterpret_cast<uint32_t*>(&t);
}

#define LDSM_T(r, addr) \
    asm volatile("ldmatrix.sync.aligned.m8n8.x4.trans.shared.b16 {%0,%1,%2,%3}, [%4];" \
        : "=r"((r)[0]), "=r"((r)[1]), "=r"((r)[2]), "=r"((r)[3]) : "r"(addr))
#define LDSM(r, addr) \
    asm volatile("ldmatrix.sync.aligned.m8n8.x4.shared.b16 {%0,%1,%2,%3}, [%4];" \
        : "=r"((r)[0]), "=r"((r)[1]), "=r"((r)[2]), "=r"((r)[3]) : "r"(addr))
#define MMA_BF16(c, a, b0, b1) \
    asm volatile("mma.sync.aligned.m16n8k16.row.col.f32.bf16.bf16.f32 " \
        "{%0,%1,%2,%3},{%4,%5,%6,%7},{%8,%9},{%0,%1,%2,%3};" \
        : "+f"((c)[0]), "+f"((c)[1]), "+f"((c)[2]), "+f"((c)[3]) \
        : "r"((a)[0]), "r"((a)[1]), "r"((a)[2]), "r"((a)[3]), "r"(b0), "r"(b1))
#define MMA_F16(c, a, b0, b1) \
    asm volatile("mma.sync.aligned.m16n8k16.row.col.f32.f16.f16.f32 " \
        "{%0,%1,%2,%3},{%4,%5,%6,%7},{%8,%9},{%0,%1,%2,%3};" \
        : "+f"((c)[0]), "+f"((c)[1]), "+f"((c)[2]), "+f"((c)[3]) \
        : "r"((a)[0]), "r"((a)[1]), "r"((a)[2]), "r"((a)[3]), "r"(b0), "r"(b1))
#define CP16(dst, src) \
    asm volatile("cp.async.cg.shared.global [%0], [%1], 16;" :: "r"(dst), "l"(src))
#define CP_COMMIT()  asm volatile("cp.async.commit_group;" ::: "memory")
#define CP_WAIT0()   asm volatile("cp.async.wait_group 0;" ::: "memory")

__device__ __forceinline__ void split_store(char* dst_h, char* dst_l, uint32_t off, float4 v) {
    __nv_bfloat16 h0 = __float2bfloat16(v.x), h1 = __float2bfloat16(v.y);
    __nv_bfloat16 h2 = __float2bfloat16(v.z), h3 = __float2bfloat16(v.w);
    __nv_bfloat16 l0 = __float2bfloat16(v.x - __bfloat162float(h0));
    __nv_bfloat16 l1 = __float2bfloat16(v.y - __bfloat162float(h1));
    __nv_bfloat16 l2 = __float2bfloat16(v.z - __bfloat162float(h2));
    __nv_bfloat16 l3 = __float2bfloat16(v.w - __bfloat162float(h3));
    *(uint2*)(dst_h + off) = make_uint2(bf2u(h0, h1), bf2u(h2, h3));
    *(uint2*)(dst_l + off) = make_uint2(bf2u(l0, l1), bf2u(l2, l3));
}

// ---------------- prep: Wv -> WvT fp16 [n][k]  AND  pack [Woff|Wattn|0] ----------------
__global__ __launch_bounds__(256) void prep_kernel(
    const float* __restrict__ Wv,
    const float* __restrict__ Woff, const float* __restrict__ Wattn)
{
    if (blockIdx.x < 256) {
        int idx = blockIdx.x * 256 + threadIdx.x;   // n*256 + k
        int n = idx >> 8, k = idx & 255;
        g_bhi[idx] = __float2half(Wv[k * DD + n]);
    } else {
        int idx = (blockIdx.x - 256) * 256 + threadIdx.x;   // 0..32767
        int k = idx >> 7, n = idx & 127;
        float v = (n < 64) ? Woff[k * 64 + n] : (n < 96 ? Wattn[k * 32 + (n - 64)] : 0.f);
        g_woa[idx] = v;
    }
}

// =====================================================================
// gemm_core: C[m0.., n0..n0+128] = A[M x 256] @ B[256 x ldb] + bias (+R)
// bf16 3-term split, CTA 64 x 128, 8 warps = 2m x 4n. SINGLE-buffered
// smem (53.2 KB) so it fits inside the 66.5 KB merged-kernel budget.
// =====================================================================
#define S_APITCH 72
#define S_BPITCH 136
#define S_AB(hl) ((hl) * 9216)                   // 0, 9216
#define S_BB(hl) (18432 + (hl) * 17408)          // 18432, 35840
#define S_SMEM 53248

template <bool RES>
__device__ __forceinline__ void gemm_core(
    const float* __restrict__ A, const float* __restrict__ Bm,
    const float* __restrict__ bias, const float* __restrict__ Rm,
    float* __restrict__ C, int M, int n0, int m0, int ldb, int ldc,
    char* smem)
{
    const uint32_t sb = smem_u32(smem);
    const int tid = threadIdx.x;
    const int lane = tid & 31;
    const int wid = tid >> 5;
    const int warp_m = wid & 1;
    const int warp_n = wid >> 1;

    const int tile = lane >> 3;
    uint32_t aoff[2];
#pragma unroll
    for (int mf = 0; mf < 2; mf++) {
        int ml = warp_m * 32 + mf * 16 + ((tile & 1) << 3) + (lane & 7);
        int kcol = (tile & 2) << 2;
        aoff[mf] = (uint32_t)(ml * S_APITCH + kcol) * 2;
    }
    uint32_t boff[2];
#pragma unroll
    for (int q = 0; q < 2; q++) {
        int kr = (lane & 7) + ((tile & 2) << 2);
        int nc = warp_n * 32 + q * 16 + ((tile & 1) << 3);
        boff[q] = (uint32_t)(kr * S_BPITCH + nc) * 2;
    }

    float acc[2][4][4];
#pragma unroll
    for (int i = 0; i < 2; i++)
#pragma unroll
        for (int j = 0; j < 4; j++)
#pragma unroll
            for (int r = 0; r < 4; r++) acc[i][j][r] = 0.f;

    float4 rA[4], rB[8];

    for (int kc = 0; kc < 4; kc++) {
        const int k0 = kc * 64;
        // global -> regs
#pragma unroll
        for (int p = 0; p < 4; p++) {
            int idx = tid + p * 256;
            int m = idx >> 4, k4 = (idx & 15) << 2;
            rA[p] = (m0 + m < M) ? *(const float4*)(A + (long)(m0 + m) * DD + k0 + k4)
                                 : make_float4(0.f, 0.f, 0.f, 0.f);
        }
#pragma unroll
        for (int p = 0; p < 8; p++) {
            int idx = tid + p * 256;
            int k = idx >> 5, n4 = (idx & 31) << 2;
            rB[p] = *(const float4*)(Bm + (long)(k0 + k) * ldb + n0 + n4);
        }
        if (kc) __syncthreads();    // previous chunk's compute done
        // regs -> smem (split)
#pragma unroll
        for (int p = 0; p < 4; p++) {
            int idx = tid + p * 256;
            int m = idx >> 4, k4 = (idx & 15) << 2;
            split_store(smem + S_AB(0), smem + S_AB(1),
                        (uint32_t)(m * S_APITCH + k4) * 2, rA[p]);
        }
#pragma unroll
        for (int p = 0; p < 8; p++) {
            int idx = tid + p * 256;
            int k = idx >> 5, n4 = (idx & 31) << 2;
            split_store(smem + S_BB(0), smem + S_BB(1),
                        (uint32_t)(k * S_BPITCH + n4) * 2, rB[p]);
        }
        __syncthreads();

        const uint32_t Ah = sb + S_AB(0), Al = sb + S_AB(1);
        const uint32_t Bh = sb + S_BB(0), Bl = sb + S_BB(1);
#pragma unroll
        for (int ks = 0; ks < 4; ks++) {
            uint32_t ah[2][4], al[2][4], bh[2][4], bl[2][4];
#pragma unroll
            for (int mf = 0; mf < 2; mf++) {
                LDSM(ah[mf], Ah + aoff[mf] + ks * 32);
                LDSM(al[mf], Al + aoff[mf] + ks * 32);
            }
#pragma unroll
            for (int q = 0; q < 2; q++) {
                LDSM_T(bh[q], Bh + boff[q] + ks * (16 * S_BPITCH * 2));
                LDSM_T(bl[q], Bl + boff[q] + ks * (16 * S_BPITCH * 2));
            }
#pragma unroll
            for (int mf = 0; mf < 2; mf++)
#pragma unroll
                for (int nf = 0; nf < 4; nf++) {
                    int q = nf >> 1, h = nf & 1;
                    MMA_BF16(acc[mf][nf], ah[mf], bh[q][h], bh[q][h + 2]);
                    MMA_BF16(acc[mf][nf], ah[mf], bl[q][h], bl[q][h + 2]);
                    MMA_BF16(acc[mf][nf], al[mf], bh[q][h], bh[q][h + 2]);
                }
        }
    }

#pragma unroll
    for (int mf = 0; mf < 2; mf++) {
        int mrow = warp_m * 32 + mf * 16 + (lane >> 2);
#pragma unroll
        for (int nf = 0; nf < 4; nf++) {
            int n = warp_n * 32 + nf * 8 + (lane & 3) * 2;
            float2 bb = *(const float2*)(bias + n0 + n);
            float2 s0 = make_float2(acc[mf][nf][0] + bb.x, acc[mf][nf][1] + bb.y);
            float2 s1 = make_float2(acc[mf][nf][2] + bb.x, acc[mf][nf][3] + bb.y);
            if (RES) {
                if (m0 + mrow < M) {
                    float2 r = *(const float2*)(Rm + (long)(m0 + mrow) * ldc + n0 + n);
                    s0.x += r.x; s0.y += r.y;
                }
                if (m0 + mrow + 8 < M) {
                    float2 r = *(const float2*)(Rm + (long)(m0 + mrow + 8) * ldc + n0 + n);
                    s1.x += r.x; s1.y += r.y;
                }
            }
            if (m0 + mrow < M)
                *(float2*)(C + (long)(m0 + mrow) * ldc + n0 + n) = s0;
            if (m0 + mrow + 8 < M)
                *(float2*)(C + (long)(m0 + mrow + 8) * ldc + n0 + n) = s1;
        }
    }
}

template <bool RES>
__global__ void __launch_bounds__(256) gemm_small(
    const float* __restrict__ A, const float* __restrict__ Bm,
    const float* __restrict__ bias, const float* __restrict__ Rm,
    float* __restrict__ C, int M, int ldb, int ldc)
{
    extern __shared__ char smem[];
    gemm_core<RES>(A, Bm, bias, Rm, C, M, blockIdx.x * 128, blockIdx.y * 64,
                   ldb, ldc, smem);
}

// prep gemms + fused biases in one wave:
//   bx 0-7:  W2 = Wmo@Wo      bx 8-15: W3 = Wq@Wo     bx 16-19: Wf = Wq@woa
//   bx 20-67: biases (warp per output):
//     n<256:  b2[n] = (bq+bmo)@Wo[:,n] + bo[n]
//     n>=256: bf[n-256] = bq@woa[:,n-256] + [boff|battn|0]
__global__ void __launch_bounds__(256) prep_gemm(
    const float* __restrict__ Wmo, const float* __restrict__ Wq,
    const float* __restrict__ Wo,
    const float* __restrict__ bq, const float* __restrict__ bmo,
    const float* __restrict__ bo, const float* __restrict__ boff,
    const float* __restrict__ battn)
{
    extern __shared__ char smem[];
    int bx = blockIdx.x;
    if (bx < 8) {
        gemm_core<false>(Wmo, Wo, g_zero, nullptr, g_w2, DD,
                         (bx & 1) * 128, (bx >> 1) * 64, DD, DD, smem);
    } else if (bx < 16) {
        bx -= 8;
        gemm_core<false>(Wq, Wo, g_zero, nullptr, g_w3, DD,
                         (bx & 1) * 128, (bx >> 1) * 64, DD, DD, smem);
    } else if (bx < 20) {
        bx -= 16;
        gemm_core<false>(Wq, g_woa, g_zero, nullptr, g_wf, DD,
                         0, bx * 64, 128, 128, smem);
    } else {
        const int lane = threadIdx.x & 31;
        const int n = (bx - 20) * 8 + (threadIdx.x >> 5);   // 0..383
        float s = 0.f;
        if (n < 256) {
#pragma unroll
            for (int i = 0; i < 8; i++) {
                int k = lane + i * 32;
                s = fmaf(bq[k] + bmo[k], Wo[k * DD + n], s);
            }
        } else {
            int nn = n - 256;
#pragma unroll
            for (int i = 0; i < 8; i++) {
                int k = lane + i * 32;
                s = fmaf(bq[k], g_woa[k * 128 + nn], s);
            }
        }
#pragma unroll
        for (int d = 16; d > 0; d >>= 1)
            s += __shfl_xor_sync(0xffffffffu, s, d);
        if (lane == 0) {
            if (n < 256) {
                g_b2[n] = s + bo[n];
            } else {
                int nn = n - 256;
                float b = (nn < 64) ? boff[nn] : (nn < 96 ? battn[nn - 64] : 0.f);
                g_bf[nn] = s + b;
            }
        }
    }
}

// =====================================================================
// gemm_v body: v[b,m,:] = bev^T[b,m,:] @ WvT^T + bv (HMMA fp16, fp32 acc)
// =====================================================================
#define VA_OFF        0                                     // 32768 bytes
#define VB(buf)       (32768 + (buf) * 16384)               // ..65536
#define V_STG         32768                                 // epilogue stage
#define V_SMEM 66560

__device__ __forceinline__ void gemm_v_body(
    char* smem, const float* __restrict__ bev, const float* __restrict__ bias,
    int m0, int b)
{
    const uint32_t sb = smem_u32(smem);
    const int tid = threadIdx.x;
    const int lane = tid & 31;
    const int wid = tid >> 5;
    const int warp_m = wid & 1;
    const int warp_n = wid >> 1;

    const float* Ag = bev + (long)b * CH * HWSZ + m0;

    uint32_t b_dst_off[4], b_goff[4];
#pragma unroll
    for (int p = 0; p < 4; p++) {
        int e = tid + p * 256;
        int n = e >> 2, c = e & 3;
        b_dst_off[p] = (uint32_t)(n * 64 + ((c ^ ((n >> 1) & 3)) << 4));
        b_goff[p] = (uint32_t)(n * 256 + c * 8);
    }

#pragma unroll
    for (int p = 0; p < 4; p++)
        CP16(sb + VB(0) + b_dst_off[p], (const void*)(g_bhi + b_goff[p]));
    CP_COMMIT();

#pragma unroll 4
    for (int p = 0; p < 16; p++) {
        int idx = tid + p * 256;
        int k = idx >> 4;
        int m4 = (idx & 15) << 2;
        float4 v = *(const float4*)(Ag + (long)k * HWSZ + m4);
        int c = m4 >> 3;
        uint32_t off = (uint32_t)(k * 128 + ((c ^ (k & 7)) << 4) + ((m4 & 4) << 1));
        *(uint2*)(smem + VA_OFF + off) = make_uint2(
            h2u(__float2half(v.x), __float2half(v.y)),
            h2u(__float2half(v.z), __float2half(v.w)));
    }

    const int tile = lane >> 3;
    const int kl = (lane & 7) + ((tile & 2) << 2);
    uint32_t aoff[2];
#pragma unroll
    for (int mf = 0; mf < 2; mf++) {
        int c = (warp_m * 32 + mf * 16 + ((tile & 1) << 3)) >> 3;
        aoff[mf] = (uint32_t)(kl * 128 + (((c ^ (kl & 7)) & 7) << 4));
    }
    uint32_t boff[4];
#pragma unroll
    for (int q = 0; q < 4; q++) {
        int n = warp_n * 64 + q * 16 + ((tile & 1) << 3) + (lane & 7);
        int c = (tile & 2) >> 1;
        boff[q] = (uint32_t)(n * 64 + ((c ^ ((n >> 1) & 3)) << 4));
    }

    float acc[2][8][4];
#pragma unroll
    for (int i = 0; i < 2; i++)
#pragma unroll
        for (int j = 0; j < 8; j++)
#pragma unroll
            for (int r = 0; r < 4; r++) acc[i][j][r] = 0.f;

    CP_WAIT0();
    __syncthreads();

    for (int kc = 0; kc < 8; kc++) {
        const int cur = kc & 1;
        if (kc < 7) {
            const uint32_t k0 = (uint32_t)((kc + 1) * 32);
#pragma unroll
            for (int p = 0; p < 4; p++)
                CP16(sb + VB(1 - cur) + b_dst_off[p], (const void*)(g_bhi + b_goff[p] + k0));
            CP_COMMIT();
        }

        const uint32_t Bh = sb + VB(cur);
#pragma unroll
        for (int ks = 0; ks < 2; ks++) {
            uint32_t a[2][4];
            const uint32_t akc = (uint32_t)((kc * 32 + ks * 16) * 128);
#pragma unroll
            for (int mf = 0; mf < 2; mf++)
                LDSM_T(a[mf], sb + VA_OFF + akc + aoff[mf]);

            const uint32_t ksx = (uint32_t)(ks << 5);
            uint32_t bh[2][4];
            LDSM(bh[0], Bh + (boff[0] ^ ksx));
#pragma unroll
            for (int q = 0; q < 4; q++) {
                const int bc = q & 1, bn_ = bc ^ 1;
                if (q < 3)
                    LDSM(bh[bn_], Bh + (boff[q + 1] ^ ksx));
#pragma unroll
                for (int h = 0; h < 2; h++) {
                    const int nf = q * 2 + h;
#pragma unroll
                    for (int mf = 0; mf < 2; mf++)
                        MMA_F16(acc[mf][nf], a[mf], bh[bc][h], bh[bc][h + 2]);
                }
            }
        }

        if (kc < 7) CP_WAIT0();
        __syncthreads();
    }

    char* stg = smem + V_STG;
#pragma unroll
    for (int mf = 0; mf < 2; mf++) {
        int mrow = warp_m * 32 + mf * 16 + (lane >> 2);
#pragma unroll
        for (int nf = 0; nf < 8; nf++) {
            int n = warp_n * 64 + nf * 8 + (lane & 3) * 2;
            float2 bb = *(const float2*)(bias + n);
            __half2 v0 = __floats2half2_rn(acc[mf][nf][0] + bb.x, acc[mf][nf][1] + bb.y);
            __half2 v1 = __floats2half2_rn(acc[mf][nf][2] + bb.x, acc[mf][nf][3] + bb.y);
            *(__half2*)(stg + mrow * 528 + n * 2) = v0;
            *(__half2*)(stg + (mrow + 8) * 528 + n * 2) = v1;
        }
    }
    __syncthreads();
    __half* vout = g_vh + ((long)b * HWSZ + m0) * DD;
#pragma unroll
    for (int i = 0; i < 8; i++) {
        int cid = tid + i * 256;
        int r = cid >> 5, c16 = cid & 31;
        *(uint4*)((char*)vout + (long)r * 512 + c16 * 16) =
            *(const uint4*)(stg + r * 528 + c16 * 16);
    }
}

// =====================================================================
// main_kernel: blocks 0..170 -> proj (qo / oa); blocks 171.. -> gemm_v
// =====================================================================
__global__ void __launch_bounds__(256, 2) main_kernel(
    const float* __restrict__ bev, const float* __restrict__ bias,
    const float* __restrict__ query)
{
    extern __shared__ char smem[];
    if (blockIdx.x < 171) {
        const int pid = blockIdx.x;
        const int bx = pid % 3, by = pid / 3;            // by 0..56
        if (bx < 2)
            gemm_core<false>(query, g_w3, g_b2, nullptr, g_qo, BB * NQ,
                             bx * 128, by * 64, DD, DD, smem);
        else
            gemm_core<false>(query, g_wf, g_bf, nullptr, g_oa, BB * NQ,
                             0, by * 64, 128, 128, smem);
    } else {
        const int bid = blockIdx.x - 171;
        gemm_v_body(smem, bev, bias, (bid % 625) * 64, bid / 625);
    }
}

// ---------------- Bezier + bilinear sampling + softmax + weighted sum ----------------
__global__ __launch_bounds__(256) void sample_kernel(
    const float* __restrict__ ctrl, const float* __restrict__ pc)
{
    __shared__ float s_ctrl[8];
    __shared__ float s_off[64];
    __shared__ float s_aw[32];
    __shared__ int   s_idx[320][4];
    __shared__ float s_w[320][4];

    const int bn = blockIdx.x;
    const int b = bn / NQ;
    const int tid = threadIdx.x;

    if (tid < 8)  s_ctrl[tid] = ctrl[(long)bn * 8 + tid];
    else if (tid >= 32 && tid < 96) s_off[tid - 32] = g_oa[(long)bn * 128 + (tid - 32)];
    else if (tid >= 96 && tid < 128) s_aw[tid - 96] = g_oa[(long)bn * 128 + 64 + (tid - 96)];
    __syncthreads();

    if (tid < 32) {
        float x = s_aw[tid];
        float m = x;
        m = fmaxf(m, __shfl_xor_sync(0xffffffffu, m, 1));
        m = fmaxf(m, __shfl_xor_sync(0xffffffffu, m, 2));
        float e = expf(x - m);
        float s = e;
        s += __shfl_xor_sync(0xffffffffu, s, 1);
        s += __shfl_xor_sync(0xffffffffu, s, 2);
        s_aw[tid] = e / s;
    }
    __syncthreads();

    const float p0 = pc[0], p1 = pc[1];
    const float invx = 1.f / (pc[3] - p0);
    const float invy = 1.f / (pc[4] - p1);

    for (int it = tid; it < 320; it += 256) {
        const int h = it / 40;
        const int kp = it - h * 40;
        const int k = kp >> 2;
        const int p = kp & 3;

        float t = (float)k * (1.0f / (NK - 1));
        float u = 1.f - t;
        float b0 = u * u * u, b1 = 3.f * u * u * t, b2 = 3.f * u * t * t, b3 = t * t * t;
        float px = b0 * s_ctrl[0] + b1 * s_ctrl[2] + b2 * s_ctrl[4] + b3 * s_ctrl[6];
        float py = b0 * s_ctrl[1] + b1 * s_ctrl[3] + b2 * s_ctrl[5] + b3 * s_ctrl[7];
        float nx = fminf(fmaxf((px - p0) * invx, 0.01f), 0.99f);
        float ny = fminf(fmaxf((py - p1) * invy, 0.01f), 0.99f);

        float gx = (nx + s_off[h * 8 + p * 2 + 0] * (1.f / WW)) * WW - 0.5f;
        float gy = (ny + s_off[h * 8 + p * 2 + 1] * (1.f / HH)) * HH - 0.5f;
        float fx = floorf(gx), fy = floorf(gy);
        float wx = gx - fx, wy = gy - fy;
        int xi = (int)fx, yi = (int)fy;
        float ap = s_aw[h * 4 + p];

#pragma unroll
        for (int c = 0; c < 4; c++) {
            int dx = c & 1, dy = c >> 1;
            int ix = xi + dx, iy = yi + dy;
            bool valid = (ix >= 0) & (ix < WW) & (iy >= 0) & (iy < HH);
            float wgt = valid ? ap * (dx ? wx : 1.f - wx) * (dy ? wy : 1.f - wy) : 0.f;
            int cx = min(max(ix, 0), WW - 1);
            int cy = min(max(iy, 0), HH - 1);
            s_w[it][c] = wgt;
            s_idx[it][c] = cy * WW + cx;
        }
    }
    __syncthreads();

    const int h = tid >> 5, lane = tid & 31;
    const __half* vb = g_vh + (long)b * HWSZ * DD + h * HDIM + lane;
    float acc = 0.f;
    const int base = h * 40;
#pragma unroll 4
    for (int i = 0; i < 40; i++) {
#pragma unroll
        for (int c = 0; c < 4; c++) {
            float w = s_w[base + i][c];
            int idx = s_idx[base + i][c];
            acc = fmaf(w, __half2float(vb[(long)idx * DD]), acc);
        }
    }
    g_s[(long)bn * DD + h * HDIM + lane] = acc;
}

// ---------------- launch ----------------
extern "C" void kernel_launch(void* const* d_in, const int* in_sizes, int n_in,
                              void* d_out, int out_size)
{
    const float* query = (const float*)d_in[0];
    const float* ctrl  = (const float*)d_in[1];
    const float* bev   = (const float*)d_in[2];
    const float* pc    = (const float*)d_in[4];
    const float* Wq    = (const float*)d_in[5];
    const float* bq    = (const float*)d_in[6];
    const float* Wv    = (const float*)d_in[7];
    const float* bv    = (const float*)d_in[8];
    const float* Woff  = (const float*)d_in[9];
    const float* boff  = (const float*)d_in[10];
    const float* Wattn = (const float*)d_in[11];
    const float* battn = (const float*)d_in[12];
    const float* Wmo   = (const float*)d_in[13];
    const float* bmo   = (const float*)d_in[14];
    const float* Wo    = (const float*)d_in[15];
    const float* bo    = (const float*)d_in[16];
    float* out = (float*)d_out;

    float *ps, *pqo, *pw2, *pzero;
    cudaGetSymbolAddress((void**)&ps, g_s);
    cudaGetSymbolAddress((void**)&pqo, g_qo);
    cudaGetSymbolAddress((void**)&pw2, g_w2);
    cudaGetSymbolAddress((void**)&pzero, g_zero);

    cudaFuncSetAttribute(main_kernel, cudaFuncAttributeMaxDynamicSharedMemorySize, V_SMEM);
    cudaFuncSetAttribute(gemm_small<true>, cudaFuncAttributeMaxDynamicSharedMemorySize, S_SMEM);
    cudaFuncSetAttribute(prep_gemm, cudaFuncAttributeMaxDynamicSharedMemorySize, S_SMEM);

    const int Mq = BB * NQ;                     // 3600

    // Wv conversion + [Woff|Wattn|0] packing
    prep_kernel<<<384, 256>>>(Wv, Woff, Wattn);
    // W2, W3, Wf gemms + fused biases in one wave
    prep_gemm<<<68, 256, S_SMEM>>>(Wmo, Wq, Wo, bq, bmo, bo, boff, battn);

    // merged: proj (qo, oa) + gemm_v (v) in one grid
    main_kernel<<<171 + (HWSZ / 64) * BB, 256, V_SMEM>>>(bev, bv, query);

    // bezier + softmax + bilinear sampling + attention-weighted sum
    sample_kernel<<<BB * NQ, 256>>>(ctrl, pc);

    // out = s@W2 + qo   (single fused tail gemm)
    gemm_small<true><<<dim3(2, (Mq + 63) / 64), 256, S_SMEM>>>(
        ps, pw2, pzero, pqo, out, Mq, DD, DD);
}

// round 15
// speedup vs baseline: 1.1978x; 1.0209x over previous
#include <cuda_runtime.h>
#include <cuda_bf16.h>
#include <cuda_fp16.h>
#include <cstdint>
#include <math.h>

// Problem constants (fixed shapes)
#define BB      4
#define NQ      900
#define DD      256
#define CH      256
#define HH      200
#define WW      200
#define HWSZ    40000
#define NHEADS  8
#define HDIM    32
#define NK      10
#define NPTS    4

// ---------------- scratch (device globals; no runtime allocation) ----------------
__device__ __half g_vh[(long)BB * HWSZ * DD];    // projected BEV values (fp16)
__device__ float g_oa [BB * NQ * 128];           // fused offsets(64)+attn logits(32)+pad
__device__ float g_qo [BB * NQ * DD];            // query@W3 + b2 (residual-through-Wo)
__device__ float g_s  [BB * NQ * DD];
__device__ __half g_bhi[DD * CH];                // WvT [n][k] fp16
__device__ float g_woa[DD * 128];                // packed [Woff | Wattn | 0] fp32 [k][n]
__device__ float g_wf [DD * 128];                // Wq @ woa  [k][n]
__device__ float g_w2 [DD * DD];                 // Wmo @ Wo
__device__ float g_w3 [DD * DD];                 // Wq @ Wo
__device__ float g_bf [128];                     // bq @ woa + [boff|battn|0]
__device__ float g_b2 [DD];                      // (bq+bmo) @ Wo + bo
__device__ float g_zero[DD];                     // stays zero

// ---------------- helpers ----------------
__device__ __forceinline__ uint32_t smem_u32(const void* p) {
    uint32_t a;
    asm("{ .reg .u64 t; cvta.to.shared.u64 t, %1; cvt.u32.u64 %0, t; }" : "=r"(a) : "l"(p));
    return a;
}
__device__ __forceinline__ uint32_t bf2u(__nv_bfloat16 a, __nv_bfloat16 b) {
    __nv_bfloat162 t(a, b);
    return *reinterpret_cast<uint32_t*>(&t);
}
__device__ __forceinline__ uint32_t h2u(__half a, __half b) {
    __half2 t(a, b);
    return *reinterpret_cast<uint32_t*>(&t);
}

#define LDSM_T(r, addr) \
    asm volatile("ldmatrix.sync.aligned.m8n8.x4.trans.shared.b16 {%0,%1,%2,%3}, [%4];" \
        : "=r"((r)[0]), "=r"((r)[1]), "=r"((r)[2]), "=r"((r)[3]) : "r"(addr))
#define LDSM(r, addr) \
    asm volatile("ldmatrix.sync.aligned.m8n8.x4.shared.b16 {%0,%1,%2,%3}, [%4];" \
        : "=r"((r)[0]), "=r"((r)[1]), "=r"((r)[2]), "=r"((r)[3]) : "r"(addr))
#define MMA_BF16(c, a, b0, b1) \
    asm volatile("mma.sync.aligned.m16n8k16.row.col.f32.bf16.bf16.f32 " \
        "{%0,%1,%2,%3},{%4,%5,%6,%7},{%8,%9},{%0,%1,%2,%3};" \
        : "+f"((c)[0]), "+f"((c)[1]), "+f"((c)[2]), "+f"((c)[3]) \
        : "r"((a)[0]), "r"((a)[1]), "r"((a)[2]), "r"((a)[3]), "r"(b0), "r"(b1))
#define MMA_F16(c, a, b0, b1) \
    asm volatile("mma.sync.aligned.m16n8k16.row.col.f32.f16.f16.f32 " \
        "{%0,%1,%2,%3},{%4,%5,%6,%7},{%8,%9},{%0,%1,%2,%3};" \
        : "+f"((c)[0]), "+f"((c)[1]), "+f"((c)[2]), "+f"((c)[3]) \
        : "r"((a)[0]), "r"((a)[1]), "r"((a)[2]), "r"((a)[3]), "r"(b0), "r"(b1))
#define CP16(dst, src) \
    asm volatile("cp.async.cg.shared.global [%0], [%1], 16;" :: "r"(dst), "l"(src))
#define CP_COMMIT()  asm volatile("cp.async.commit_group;" ::: "memory")
#define CP_WAIT0()   asm volatile("cp.async.wait_group 0;" ::: "memory")

__device__ __forceinline__ void split_store(char* dst_h, char* dst_l, uint32_t off, float4 v) {
    __nv_bfloat16 h0 = __float2bfloat16(v.x), h1 = __float2bfloat16(v.y);
    __nv_bfloat16 h2 = __float2bfloat16(v.z), h3 = __float2bfloat16(v.w);
    __nv_bfloat16 l0 = __float2bfloat16(v.x - __bfloat162float(h0));
    __nv_bfloat16 l1 = __float2bfloat16(v.y - __bfloat162float(h1));
    __nv_bfloat16 l2 = __float2bfloat16(v.z - __bfloat162float(h2));
    __nv_bfloat16 l3 = __float2bfloat16(v.w - __bfloat162float(h3));
    *(uint2*)(dst_h + off) = make_uint2(bf2u(h0, h1), bf2u(h2, h3));
    *(uint2*)(dst_l + off) = make_uint2(bf2u(l0, l1), bf2u(l2, l3));
}

// ---------------- prep: Wv -> WvT fp16 [n][k]  AND  pack [Woff|Wattn|0] ----------------
__global__ __launch_bounds__(256) void prep_kernel(
    const float* __restrict__ Wv,
    const float* __restrict__ Woff, const float* __restrict__ Wattn)
{
    if (blockIdx.x < 256) {
        int idx = blockIdx.x * 256 + threadIdx.x;   // n*256 + k
        int n = idx >> 8, k = idx & 255;
        g_bhi[idx] = __float2half(Wv[k * DD + n]);
    } else {
        int idx = (blockIdx.x - 256) * 256 + threadIdx.x;   // 0..32767
        int k = idx >> 7, n = idx & 127;
        float v = (n < 64) ? Woff[k * 64 + n] : (n < 96 ? Wattn[k * 32 + (n - 64)] : 0.f);
        g_woa[idx] = v;
    }
}

// =====================================================================
// gemm_core: C[m0.., n0..n0+128] = A[M x 256] @ B[256 x ldb] + bias (+R)
// bf16 3-term split, CTA 64 x 128, 8 warps = 2m x 4n. SINGLE-buffered.
// =====================================================================
#define S_APITCH 72
#define S_BPITCH 136
#define S_AB(hl) ((hl) * 9216)                   // 0, 9216
#define S_BB(hl) (18432 + (hl) * 17408)          // 18432, 35840
#define S_SMEM 53248

template <bool RES>
__device__ __forceinline__ void gemm_core(
    const float* __restrict__ A, const float* __restrict__ Bm,
    const float* __restrict__ bias, const float* __restrict__ Rm,
    float* __restrict__ C, int M, int n0, int m0, int ldb, int ldc,
    char* smem)
{
    const uint32_t sb = smem_u32(smem);
    const int tid = threadIdx.x;
    const int lane = tid & 31;
    const int wid = tid >> 5;
    const int warp_m = wid & 1;
    const int warp_n = wid >> 1;

    const int tile = lane >> 3;
    uint32_t aoff[2];
#pragma unroll
    for (int mf = 0; mf < 2; mf++) {
        int ml = warp_m * 32 + mf * 16 + ((tile & 1) << 3) + (lane & 7);
        int kcol = (tile & 2) << 2;
        aoff[mf] = (uint32_t)(ml * S_APITCH + kcol) * 2;
    }
    uint32_t boff[2];
#pragma unroll
    for (int q = 0; q < 2; q++) {
        int kr = (lane & 7) + ((tile & 2) << 2);
        int nc = warp_n * 32 + q * 16 + ((tile & 1) << 3);
        boff[q] = (uint32_t)(kr * S_BPITCH + nc) * 2;
    }

    float acc[2][4][4];
#pragma unroll
    for (int i = 0; i < 2; i++)
#pragma unroll
        for (int j = 0; j < 4; j++)
#pragma unroll
            for (int r = 0; r < 4; r++) acc[i][j][r] = 0.f;

    float4 rA[4], rB[8];

    for (int kc = 0; kc < 4; kc++) {
        const int k0 = kc * 64;
#pragma unroll
        for (int p = 0; p < 4; p++) {
            int idx = tid + p * 256;
            int m = idx >> 4, k4 = (idx & 15) << 2;
            rA[p] = (m0 + m < M) ? *(const float4*)(A + (long)(m0 + m) * DD + k0 + k4)
                                 : make_float4(0.f, 0.f, 0.f, 0.f);
        }
#pragma unroll
        for (int p = 0; p < 8; p++) {
            int idx = tid + p * 256;
            int k = idx >> 5, n4 = (idx & 31) << 2;
            rB[p] = *(const float4*)(Bm + (long)(k0 + k) * ldb + n0 + n4);
        }
        if (kc) __syncthreads();
#pragma unroll
        for (int p = 0; p < 4; p++) {
            int idx = tid + p * 256;
            int m = idx >> 4, k4 = (idx & 15) << 2;
            split_store(smem + S_AB(0), smem + S_AB(1),
                        (uint32_t)(m * S_APITCH + k4) * 2, rA[p]);
        }
#pragma unroll
        for (int p = 0; p < 8; p++) {
            int idx = tid + p * 256;
            int k = idx >> 5, n4 = (idx & 31) << 2;
            split_store(smem + S_BB(0), smem + S_BB(1),
                        (uint32_t)(k * S_BPITCH + n4) * 2, rB[p]);
        }
        __syncthreads();

        const uint32_t Ah = sb + S_AB(0), Al = sb + S_AB(1);
        const uint32_t Bh = sb + S_BB(0), Bl = sb + S_BB(1);
#pragma unroll
        for (int ks = 0; ks < 4; ks++) {
            uint32_t ah[2][4], al[2][4], bh[2][4], bl[2][4];
#pragma unroll
            for (int mf = 0; mf < 2; mf++) {
                LDSM(ah[mf], Ah + aoff[mf] + ks * 32);
                LDSM(al[mf], Al + aoff[mf] + ks * 32);
            }
#pragma unroll
            for (int q = 0; q < 2; q++) {
                LDSM_T(bh[q], Bh + boff[q] + ks * (16 * S_BPITCH * 2));
                LDSM_T(bl[q], Bl + boff[q] + ks * (16 * S_BPITCH * 2));
            }
#pragma unroll
            for (int mf = 0; mf < 2; mf++)
#pragma unroll
                for (int nf = 0; nf < 4; nf++) {
                    int q = nf >> 1, h = nf & 1;
                    MMA_BF16(acc[mf][nf], ah[mf], bh[q][h], bh[q][h + 2]);
                    MMA_BF16(acc[mf][nf], ah[mf], bl[q][h], bl[q][h + 2]);
                    MMA_BF16(acc[mf][nf], al[mf], bh[q][h], bh[q][h + 2]);
                }
        }
    }

#pragma unroll
    for (int mf = 0; mf < 2; mf++) {
        int mrow = warp_m * 32 + mf * 16 + (lane >> 2);
#pragma unroll
        for (int nf = 0; nf < 4; nf++) {
            int n = warp_n * 32 + nf * 8 + (lane & 3) * 2;
            float2 bb = *(const float2*)(bias + n0 + n);
            float2 s0 = make_float2(acc[mf][nf][0] + bb.x, acc[mf][nf][1] + bb.y);
            float2 s1 = make_float2(acc[mf][nf][2] + bb.x, acc[mf][nf][3] + bb.y);
            if (RES) {
                if (m0 + mrow < M) {
                    float2 r = *(const float2*)(Rm + (long)(m0 + mrow) * ldc + n0 + n);
                    s0.x += r.x; s0.y += r.y;
                }
                if (m0 + mrow + 8 < M) {
                    float2 r = *(const float2*)(Rm + (long)(m0 + mrow + 8) * ldc + n0 + n);
                    s1.x += r.x; s1.y += r.y;
                }
            }
            if (m0 + mrow < M)
                *(float2*)(C + (long)(m0 + mrow) * ldc + n0 + n) = s0;
            if (m0 + mrow + 8 < M)
                *(float2*)(C + (long)(m0 + mrow + 8) * ldc + n0 + n) = s1;
        }
    }
}

template <bool RES>
__global__ void __launch_bounds__(256) gemm_small(
    const float* __restrict__ A, const float* __restrict__ Bm,
    const float* __restrict__ bias, const float* __restrict__ Rm,
    float* __restrict__ C, int M, int ldb, int ldc)
{
    extern __shared__ char smem[];
    gemm_core<RES>(A, Bm, bias, Rm, C, M, blockIdx.x * 128, blockIdx.y * 64,
                   ldb, ldc, smem);
}

// prep gemms + fused biases in one wave
__global__ void __launch_bounds__(256) prep_gemm(
    const float* __restrict__ Wmo, const float* __restrict__ Wq,
    const float* __restrict__ Wo,
    const float* __restrict__ bq, const float* __restrict__ bmo,
    const float* __restrict__ bo, const float* __restrict__ boff,
    const float* __restrict__ battn)
{
    extern __shared__ char smem[];
    int bx = blockIdx.x;
    if (bx < 8) {
        gemm_core<false>(Wmo, Wo, g_zero, nullptr, g_w2, DD,
                         (bx & 1) * 128, (bx >> 1) * 64, DD, DD, smem);
    } else if (bx < 16) {
        bx -= 8;
        gemm_core<false>(Wq, Wo, g_zero, nullptr, g_w3, DD,
                         (bx & 1) * 128, (bx >> 1) * 64, DD, DD, smem);
    } else if (bx < 20) {
        bx -= 16;
        gemm_core<false>(Wq, g_woa, g_zero, nullptr, g_wf, DD,
                         0, bx * 64, 128, 128, smem);
    } else {
        const int lane = threadIdx.x & 31;
        const int n = (bx - 20) * 8 + (threadIdx.x >> 5);   // 0..383
        float s = 0.f;
        if (n < 256) {
#pragma unroll
            for (int i = 0; i < 8; i++) {
                int k = lane + i * 32;
                s = fmaf(bq[k] + bmo[k], Wo[k * DD + n], s);
            }
        } else {
            int nn = n - 256;
#pragma unroll
            for (int i = 0; i < 8; i++) {
                int k = lane + i * 32;
                s = fmaf(bq[k], g_woa[k * 128 + nn], s);
            }
        }
#pragma unroll
        for (int d = 16; d > 0; d >>= 1)
            s += __shfl_xor_sync(0xffffffffu, s, d);
        if (lane == 0) {
            if (n < 256) {
                g_b2[n] = s + bo[n];
            } else {
                int nn = n - 256;
                float b = (nn < 64) ? boff[nn] : (nn < 96 ? battn[nn - 64] : 0.f);
                g_bf[nn] = s + b;
            }
        }
    }
}

// =====================================================================
// gemm_v body: v[b,m,:] = bev^T[b,m,:] @ WvT^T + bv (HMMA fp16, fp32 acc)
// =====================================================================
#define VA_OFF        0                                     // 32768 bytes
#define VB(buf)       (32768 + (buf) * 16384)               // ..65536
#define V_STG         32768                                 // epilogue stage
#define V_SMEM 66560

__device__ __forceinline__ void gemm_v_body(
    char* smem, const float* __restrict__ bev, const float* __restrict__ bias,
    int m0, int b)
{
    const uint32_t sb = smem_u32(smem);
    const int tid = threadIdx.x;
    const int lane = tid & 31;
    const int wid = tid >> 5;
    const int warp_m = wid & 1;
    const int warp_n = wid >> 1;

    const float* Ag = bev + (long)b * CH * HWSZ + m0;

    uint32_t b_dst_off[4], b_goff[4];
#pragma unroll
    for (int p = 0; p < 4; p++) {
        int e = tid + p * 256;
        int n = e >> 2, c = e & 3;
        b_dst_off[p] = (uint32_t)(n * 64 + ((c ^ ((n >> 1) & 3)) << 4));
        b_goff[p] = (uint32_t)(n * 256 + c * 8);
    }

#pragma unroll
    for (int p = 0; p < 4; p++)
        CP16(sb + VB(0) + b_dst_off[p], (const void*)(g_bhi + b_goff[p]));
    CP_COMMIT();

#pragma unroll 4
    for (int p = 0; p < 16; p++) {
        int idx = tid + p * 256;
        int k = idx >> 4;
        int m4 = (idx & 15) << 2;
        float4 v = *(const float4*)(Ag + (long)k * HWSZ + m4);
        int c = m4 >> 3;
        uint32_t off = (uint32_t)(k * 128 + ((c ^ (k & 7)) << 4) + ((m4 & 4) << 1));
        *(uint2*)(smem + VA_OFF + off) = make_uint2(
            h2u(__float2half(v.x), __float2half(v.y)),
            h2u(__float2half(v.z), __float2half(v.w)));
    }

    const int tile = lane >> 3;
    const int kl = (lane & 7) + ((tile & 2) << 2);
    uint32_t aoff[2];
#pragma unroll
    for (int mf = 0; mf < 2; mf++) {
        int c = (warp_m * 32 + mf * 16 + ((tile & 1) << 3)) >> 3;
        aoff[mf] = (uint32_t)(kl * 128 + (((c ^ (kl & 7)) & 7) << 4));
    }
    uint32_t boff[4];
#pragma unroll
    for (int q = 0; q < 4; q++) {
        int n = warp_n * 64 + q * 16 + ((tile & 1) << 3) + (lane & 7);
        int c = (tile & 2) >> 1;
        boff[q] = (uint32_t)(n * 64 + ((c ^ ((n >> 1) & 3)) << 4));
    }

    float acc[2][8][4];
#pragma unroll
    for (int i = 0; i < 2; i++)
#pragma unroll
        for (int j = 0; j < 8; j++)
#pragma unroll
            for (int r = 0; r < 4; r++) acc[i][j][r] = 0.f;

    CP_WAIT0();
    __syncthreads();

    for (int kc = 0; kc < 8; kc++) {
        const int cur = kc & 1;
        if (kc < 7) {
            const uint32_t k0 = (uint32_t)((kc + 1) * 32);
#pragma unroll
            for (int p = 0; p < 4; p++)
                CP16(sb + VB(1 - cur) + b_dst_off[p], (const void*)(g_bhi + b_goff[p] + k0));
            CP_COMMIT();
        }

        const uint32_t Bh = sb + VB(cur);
#pragma unroll
        for (int ks = 0; ks < 2; ks++) {
            uint32_t a[2][4];
            const uint32_t akc = (uint32_t)((kc * 32 + ks * 16) * 128);
#pragma unroll
            for (int mf = 0; mf < 2; mf++)
                LDSM_T(a[mf], sb + VA_OFF + akc + aoff[mf]);

            const uint32_t ksx = (uint32_t)(ks << 5);
            uint32_t bh[2][4];
            LDSM(bh[0], Bh + (boff[0] ^ ksx));
#pragma unroll
            for (int q = 0; q < 4; q++) {
                const int bc = q & 1, bn_ = bc ^ 1;
                if (q < 3)
                    LDSM(bh[bn_], Bh + (boff[q + 1] ^ ksx));
#pragma unroll
                for (int h = 0; h < 2; h++) {
                    const int nf = q * 2 + h;
#pragma unroll
                    for (int mf = 0; mf < 2; mf++)
                        MMA_F16(acc[mf][nf], a[mf], bh[bc][h], bh[bc][h + 2]);
                }
            }
        }

        if (kc < 7) CP_WAIT0();
        __syncthreads();
    }

    char* stg = smem + V_STG;
#pragma unroll
    for (int mf = 0; mf < 2; mf++) {
        int mrow = warp_m * 32 + mf * 16 + (lane >> 2);
#pragma unroll
        for (int nf = 0; nf < 8; nf++) {
            int n = warp_n * 64 + nf * 8 + (lane & 3) * 2;
            float2 bb = *(const float2*)(bias + n);
            __half2 v0 = __floats2half2_rn(acc[mf][nf][0] + bb.x, acc[mf][nf][1] + bb.y);
            __half2 v1 = __floats2half2_rn(acc[mf][nf][2] + bb.x, acc[mf][nf][3] + bb.y);
            *(__half2*)(stg + mrow * 528 + n * 2) = v0;
            *(__half2*)(stg + (mrow + 8) * 528 + n * 2) = v1;
        }
    }
    __syncthreads();
    __half* vout = g_vh + ((long)b * HWSZ + m0) * DD;
#pragma unroll
    for (int i = 0; i < 8; i++) {
        int cid = tid + i * 256;
        int r = cid >> 5, c16 = cid & 31;
        *(uint4*)((char*)vout + (long)r * 512 + c16 * 16) =
            *(const uint4*)(stg + r * 528 + c16 * 16);
    }
}

// =====================================================================
// main_kernel: blocks 0..170 -> proj (qo / oa); blocks 171.. -> gemm_v
// =====================================================================
__global__ void __launch_bounds__(256, 2) main_kernel(
    const float* __restrict__ bev, const float* __restrict__ bias,
    const float* __restrict__ query)
{
    extern __shared__ char smem[];
    if (blockIdx.x < 171) {
        const int pid = blockIdx.x;
        const int bx = pid % 3, by = pid / 3;            // by 0..56
        if (bx < 2)
            gemm_core<false>(query, g_w3, g_b2, nullptr, g_qo, BB * NQ,
                             bx * 128, by * 64, DD, DD, smem);
        else
            gemm_core<false>(query, g_wf, g_bf, nullptr, g_oa, BB * NQ,
                             0, by * 64, 128, 128, smem);
    } else {
        const int bid = blockIdx.x - 171;
        gemm_v_body(smem, bev, bias, (bid % 625) * 64, bid / 625);
    }
}

// ---------------- Bezier + bilinear sampling + softmax + weighted sum ----------------
// Phase 2 vectorized: warp = head; half-warp A = even entries, B = odd;
// lane covers 2 channels via __half2; final cross-half-warp shuffle reduce.
__global__ __launch_bounds__(256) void sample_kernel(
    const float* __restrict__ ctrl, const float* __restrict__ pc)
{
    __shared__ float s_ctrl[8];
    __shared__ float s_off[64];
    __shared__ float s_aw[32];
    __shared__ int   s_idx[320][4];     // pre-scaled: pixel * DD (element offset)
    __shared__ float s_w[320][4];

    const int bn = blockIdx.x;
    const int b = bn / NQ;
    const int tid = threadIdx.x;

    if (tid < 8)  s_ctrl[tid] = ctrl[(long)bn * 8 + tid];
    else if (tid >= 32 && tid < 96) s_off[tid - 32] = g_oa[(long)bn * 128 + (tid - 32)];
    else if (tid >= 96 && tid < 128) s_aw[tid - 96] = g_oa[(long)bn * 128 + 64 + (tid - 96)];
    __syncthreads();

    if (tid < 32) {
        float x = s_aw[tid];
        float m = x;
        m = fmaxf(m, __shfl_xor_sync(0xffffffffu, m, 1));
        m = fmaxf(m, __shfl_xor_sync(0xffffffffu, m, 2));
        float e = expf(x - m);
        float s = e;
        s += __shfl_xor_sync(0xffffffffu, s, 1);
        s += __shfl_xor_sync(0xffffffffu, s, 2);
        s_aw[tid] = e / s;
    }
    __syncthreads();

    const float p0 = pc[0], p1 = pc[1];
    const float invx = 1.f / (pc[3] - p0);
    const float invy = 1.f / (pc[4] - p1);

    for (int it = tid; it < 320; it += 256) {
        const int h = it / 40;
        const int kp = it - h * 40;
        const int k = kp >> 2;
        const int p = kp & 3;

        float t = (float)k * (1.0f / (NK - 1));
        float u = 1.f - t;
        float b0 = u * u * u, b1 = 3.f * u * u * t, b2 = 3.f * u * t * t, b3 = t * t * t;
        float px = b0 * s_ctrl[0] + b1 * s_ctrl[2] + b2 * s_ctrl[4] + b3 * s_ctrl[6];
        float py = b0 * s_ctrl[1] + b1 * s_ctrl[3] + b2 * s_ctrl[5] + b3 * s_ctrl[7];
        float nx = fminf(fmaxf((px - p0) * invx, 0.01f), 0.99f);
        float ny = fminf(fmaxf((py - p1) * invy, 0.01f), 0.99f);

        float gx = (nx + s_off[h * 8 + p * 2 + 0] * (1.f / WW)) * WW - 0.5f;
        float gy = (ny + s_off[h * 8 + p * 2 + 1] * (1.f / HH)) * HH - 0.5f;
        float fx = floorf(gx), fy = floorf(gy);
        float wx = gx - fx, wy = gy - fy;
        int xi = (int)fx, yi = (int)fy;
        float ap = s_aw[h * 4 + p];

#pragma unroll
        for (int c = 0; c < 4; c++) {
            int dx = c & 1, dy = c >> 1;
            int ix = xi + dx, iy = yi + dy;
            bool valid = (ix >= 0) & (ix < WW) & (iy >= 0) & (iy < HH);
            float wgt = valid ? ap * (dx ? wx : 1.f - wx) * (dy ? wy : 1.f - wy) : 0.f;
            int cx = min(max(ix, 0), WW - 1);
            int cy = min(max(iy, 0), HH - 1);
            s_w[it][c] = wgt;
            s_idx[it][c] = (cy * WW + cx) * DD;
        }
    }
    __syncthreads();

    // gather: warp = head; hw = half-warp (entry parity); sl*2 = channel pair
    const int h = tid >> 5, lane = tid & 31;
    const int hw = lane >> 4, sl = lane & 15;
    const __half* vb = g_vh + (long)b * HWSZ * DD + h * HDIM + sl * 2;
    const float* wrow = &s_w[h * 40][0];
    const int* irow = &s_idx[h * 40][0];
    float ax = 0.f, ay = 0.f;
#pragma unroll 8
    for (int eb = 0; eb < 80; eb++) {
        const int e = eb * 2 + hw;
        float w = wrow[e];
        int idx = irow[e];
        __half2 hv = *(const __half2*)(vb + idx);
        float2 f = __half22float2(hv);
        ax = fmaf(w, f.x, ax);
        ay = fmaf(w, f.y, ay);
    }
    ax += __shfl_down_sync(0xffffffffu, ax, 16);
    ay += __shfl_down_sync(0xffffffffu, ay, 16);
    if (hw == 0)
        *(float2*)(g_s + (long)bn * DD + h * HDIM + sl * 2) = make_float2(ax, ay);
}

// ---------------- launch ----------------
extern "C" void kernel_launch(void* const* d_in, const int* in_sizes, int n_in,
                              void* d_out, int out_size)
{
    const float* query = (const float*)d_in[0];
    const float* ctrl  = (const float*)d_in[1];
    const float* bev   = (const float*)d_in[2];
    const float* pc    = (const float*)d_in[4];
    const float* Wq    = (const float*)d_in[5];
    const float* bq    = (const float*)d_in[6];
    const float* Wv    = (const float*)d_in[7];
    const float* bv    = (const float*)d_in[8];
    const float* Woff  = (const float*)d_in[9];
    const float* boff  = (const float*)d_in[10];
    const float* Wattn = (const float*)d_in[11];
    const float* battn = (const float*)d_in[12];
    const float* Wmo   = (const float*)d_in[13];
    const float* bmo   = (const float*)d_in[14];
    const float* Wo    = (const float*)d_in[15];
    const float* bo    = (const float*)d_in[16];
    float* out = (float*)d_out;

    float *ps, *pqo, *pw2, *pzero;
    cudaGetSymbolAddress((void**)&ps, g_s);
    cudaGetSymbolAddress((void**)&pqo, g_qo);
    cudaGetSymbolAddress((void**)&pw2, g_w2);
    cudaGetSymbolAddress((void**)&pzero, g_zero);

    cudaFuncSetAttribute(main_kernel, cudaFuncAttributeMaxDynamicSharedMemorySize, V_SMEM);
    cudaFuncSetAttribute(gemm_small<true>, cudaFuncAttributeMaxDynamicSharedMemorySize, S_SMEM);
    cudaFuncSetAttribute(prep_gemm, cudaFuncAttributeMaxDynamicSharedMemorySize, S_SMEM);

    const int Mq = BB * NQ;                     // 3600

    // Wv conversion + [Woff|Wattn|0] packing
    prep_kernel<<<384, 256>>>(Wv, Woff, Wattn);
    // W2, W3, Wf gemms + fused biases in one wave
    prep_gemm<<<68, 256, S_SMEM>>>(Wmo, Wq, Wo, bq, bmo, bo, boff, battn);

    // merged: proj (qo, oa) + gemm_v (v) in one grid
    main_kernel<<<171 + (HWSZ / 64) * BB, 256, V_SMEM>>>(bev, bv, query);

    // bezier + softmax + bilinear sampling + attention-weighted sum
    sample_kernel<<<BB * NQ, 256>>>(ctrl, pc);

    // out = s@W2 + qo   (single fused tail gemm)
    gemm_small<true><<<dim3(2, (Mq + 63) / 64), 256, S_SMEM>>>(
        ps, pw2, pzero, pqo, out, Mq, DD, DD);
}

// round 16
// speedup vs baseline: 1.2378x; 1.0334x over previous
#include <cuda_runtime.h>
#include <cuda_bf16.h>
#include <cuda_fp16.h>
#include <cstdint>
#include <math.h>

// Problem constants (fixed shapes)
#define BB      4
#define NQ      900
#define DD      256
#define CH      256
#define HH      200
#define WW      200
#define HWSZ    40000
#define NHEADS  8
#define HDIM    32
#define NK      10
#define NPTS    4

// ---------------- scratch (device globals; no runtime allocation) ----------------
__device__ __half g_vh[(long)BB * HWSZ * DD];    // projected BEV values (fp16)
__device__ float g_oa [BB * NQ * 128];           // fused offsets(64)+attn logits(32)+pad
__device__ float g_qo [BB * NQ * DD];            // query@W3 + b2 (residual-through-Wo)
__device__ float g_s  [BB * NQ * DD];
__device__ __half g_bhi[DD * CH];                // WvT [n][k] fp16
__device__ float g_woa[DD * 128];                // packed [Woff | Wattn | 0] fp32 [k][n]
__device__ float g_wf [DD * 128];                // Wq @ woa  [k][n]
__device__ float g_w2 [DD * DD];                 // Wmo @ Wo
__device__ float g_w3 [DD * DD];                 // Wq @ Wo
__device__ float g_bf [128];                     // bq @ woa + [boff|battn|0]
__device__ float g_b2 [DD];                      // (bq+bmo) @ Wo + bo
__device__ float g_zero[DD];                     // stays zero

// ---------------- helpers ----------------
__device__ __forceinline__ uint32_t smem_u32(const void* p) {
    uint32_t a;
    asm("{ .reg .u64 t; cvta.to.shared.u64 t, %1; cvt.u32.u64 %0, t; }" : "=r"(a) : "l"(p));
    return a;
}
__device__ __forceinline__ uint32_t bf2u(__nv_bfloat16 a, __nv_bfloat16 b) {
    __nv_bfloat162 t(a, b);
    return *reinterpret_cast<uint32_t*>(&t);
}
__device__ __forceinline__ uint32_t h2u(__half a, __half b) {
    __half2 t(a, b);
    return *reinterpret_cast<uint32_t*>(&t);
}

#define LDSM_T(r, addr) \
    asm volatile("ldmatrix.sync.aligned.m8n8.x4.trans.shared.b16 {%0,%1,%2,%3}, [%4];" \
        : "=r"((r)[0]), "=r"((r)[1]), "=r"((r)[2]), "=r"((r)[3]) : "r"(addr))
#define LDSM(r, addr) \
    asm volatile("ldmatrix.sync.aligned.m8n8.x4.shared.b16 {%0,%1,%2,%3}, [%4];" \
        : "=r"((r)[0]), "=r"((r)[1]), "=r"((r)[2]), "=r"((r)[3]) : "r"(addr))
#define MMA_BF16(c, a, b0, b1) \
    asm volatile("mma.sync.aligned.m16n8k16.row.col.f32.bf16.bf16.f32 " \
        "{%0,%1,%2,%3},{%4,%5,%6,%7},{%8,%9},{%0,%1,%2,%3};" \
        : "+f"((c)[0]), "+f"((c)[1]), "+f"((c)[2]), "+f"((c)[3]) \
        : "r"((a)[0]), "r"((a)[1]), "r"((a)[2]), "r"((a)[3]), "r"(b0), "r"(b1))
#define MMA_F16(c, a, b0, b1) \
    asm volatile("mma.sync.aligned.m16n8k16.row.col.f32.f16.f16.f32 " \
        "{%0,%1,%2,%3},{%4,%5,%6,%7},{%8,%9},{%0,%1,%2,%3};" \
        : "+f"((c)[0]), "+f"((c)[1]), "+f"((c)[2]), "+f"((c)[3]) \
        : "r"((a)[0]), "r"((a)[1]), "r"((a)[2]), "r"((a)[3]), "r"(b0), "r"(b1))
#define CP16(dst, src) \
    asm volatile("cp.async.cg.shared.global [%0], [%1], 16;" :: "r"(dst), "l"(src))
#define CP_COMMIT()  asm volatile("cp.async.commit_group;" ::: "memory")
#define CP_WAIT0()   asm volatile("cp.async.wait_group 0;" ::: "memory")

__device__ __forceinline__ void split_store(char* dst_h, char* dst_l, uint32_t off, float4 v) {
    __nv_bfloat16 h0 = __float2bfloat16(v.x), h1 = __float2bfloat16(v.y);
    __nv_bfloat16 h2 = __float2bfloat16(v.z), h3 = __float2bfloat16(v.w);
    __nv_bfloat16 l0 = __float2bfloat16(v.x - __bfloat162float(h0));
    __nv_bfloat16 l1 = __float2bfloat16(v.y - __bfloat162float(h1));
    __nv_bfloat16 l2 = __float2bfloat16(v.z - __bfloat162float(h2));
    __nv_bfloat16 l3 = __float2bfloat16(v.w - __bfloat162float(h3));
    *(uint2*)(dst_h + off) = make_uint2(bf2u(h0, h1), bf2u(h2, h3));
    *(uint2*)(dst_l + off) = make_uint2(bf2u(l0, l1), bf2u(l2, l3));
}

// ---------------- prep: Wv -> WvT fp16 [n][k]  AND  pack [Woff|Wattn|0] ----------------
__global__ __launch_bounds__(256) void prep_kernel(
    const float* __restrict__ Wv,
    const float* __restrict__ Woff, const float* __restrict__ Wattn)
{
    if (blockIdx.x < 256) {
        int idx = blockIdx.x * 256 + threadIdx.x;   // n*256 + k
        int n = idx >> 8, k = idx & 255;
        g_bhi[idx] = __float2half(Wv[k * DD + n]);
    } else {
        int idx = (blockIdx.x - 256) * 256 + threadIdx.x;   // 0..32767
        int k = idx >> 7, n = idx & 127;
        float v = (n < 64) ? Woff[k * 64 + n] : (n < 96 ? Wattn[k * 32 + (n - 64)] : 0.f);
        g_woa[idx] = v;
    }
}

// =====================================================================
// gemm_core: C[m0.., n0..n0+128] = A[M x 256] @ B[256 x ldb] + bias (+R)
// bf16 3-term split, CTA 64 x 128, 8 warps = 2m x 4n. SINGLE-buffered.
// =====================================================================
#define S_APITCH 72
#define S_BPITCH 136
#define S_AB(hl) ((hl) * 9216)                   // 0, 9216
#define S_BB(hl) (18432 + (hl) * 17408)          // 18432, 35840
#define S_SMEM 53248

template <bool RES>
__device__ __forceinline__ void gemm_core(
    const float* __restrict__ A, const float* __restrict__ Bm,
    const float* __restrict__ bias, const float* __restrict__ Rm,
    float* __restrict__ C, int M, int n0, int m0, int ldb, int ldc,
    char* smem)
{
    const uint32_t sb = smem_u32(smem);
    const int tid = threadIdx.x;
    const int lane = tid & 31;
    const int wid = tid >> 5;
    const int warp_m = wid & 1;
    const int warp_n = wid >> 1;

    const int tile = lane >> 3;
    uint32_t aoff[2];
#pragma unroll
    for (int mf = 0; mf < 2; mf++) {
        int ml = warp_m * 32 + mf * 16 + ((tile & 1) << 3) + (lane & 7);
        int kcol = (tile & 2) << 2;
        aoff[mf] = (uint32_t)(ml * S_APITCH + kcol) * 2;
    }
    uint32_t boff[2];
#pragma unroll
    for (int q = 0; q < 2; q++) {
        int kr = (lane & 7) + ((tile & 2) << 2);
        int nc = warp_n * 32 + q * 16 + ((tile & 1) << 3);
        boff[q] = (uint32_t)(kr * S_BPITCH + nc) * 2;
    }

    float acc[2][4][4];
#pragma unroll
    for (int i = 0; i < 2; i++)
#pragma unroll
        for (int j = 0; j < 4; j++)
#pragma unroll
            for (int r = 0; r < 4; r++) acc[i][j][r] = 0.f;

    float4 rA[4], rB[8];

    for (int kc = 0; kc < 4; kc++) {
        const int k0 = kc * 64;
#pragma unroll
        for (int p = 0; p < 4; p++) {
            int idx = tid + p * 256;
            int m = idx >> 4, k4 = (idx & 15) << 2;
            rA[p] = (m0 + m < M) ? *(const float4*)(A + (long)(m0 + m) * DD + k0 + k4)
                                 : make_float4(0.f, 0.f, 0.f, 0.f);
        }
#pragma unroll
        for (int p = 0; p < 8; p++) {
            int idx = tid + p * 256;
            int k = idx >> 5, n4 = (idx & 31) << 2;
            rB[p] = *(const float4*)(Bm + (long)(k0 + k) * ldb + n0 + n4);
        }
        if (kc) __syncthreads();
#pragma unroll
        for (int p = 0; p < 4; p++) {
            int idx = tid + p * 256;
            int m = idx >> 4, k4 = (idx & 15) << 2;
            split_store(smem + S_AB(0), smem + S_AB(1),
                        (uint32_t)(m * S_APITCH + k4) * 2, rA[p]);
        }
#pragma unroll
        for (int p = 0; p < 8; p++) {
            int idx = tid + p * 256;
            int k = idx >> 5, n4 = (idx & 31) << 2;
            split_store(smem + S_BB(0), smem + S_BB(1),
                        (uint32_t)(k * S_BPITCH + n4) * 2, rB[p]);
        }
        __syncthreads();

        const uint32_t Ah = sb + S_AB(0), Al = sb + S_AB(1);
        const uint32_t Bh = sb + S_BB(0), Bl = sb + S_BB(1);
#pragma unroll
        for (int ks = 0; ks < 4; ks++) {
            uint32_t ah[2][4], al[2][4], bh[2][4], bl[2][4];
#pragma unroll
            for (int mf = 0; mf < 2; mf++) {
                LDSM(ah[mf], Ah + aoff[mf] + ks * 32);
                LDSM(al[mf], Al + aoff[mf] + ks * 32);
            }
#pragma unroll
            for (int q = 0; q < 2; q++) {
                LDSM_T(bh[q], Bh + boff[q] + ks * (16 * S_BPITCH * 2));
                LDSM_T(bl[q], Bl + boff[q] + ks * (16 * S_BPITCH * 2));
            }
#pragma unroll
            for (int mf = 0; mf < 2; mf++)
#pragma unroll
                for (int nf = 0; nf < 4; nf++) {
                    int q = nf >> 1, h = nf & 1;
                    MMA_BF16(acc[mf][nf], ah[mf], bh[q][h], bh[q][h + 2]);
                    MMA_BF16(acc[mf][nf], ah[mf], bl[q][h], bl[q][h + 2]);
                    MMA_BF16(acc[mf][nf], al[mf], bh[q][h], bh[q][h + 2]);
                }
        }
    }

#pragma unroll
    for (int mf = 0; mf < 2; mf++) {
        int mrow = warp_m * 32 + mf * 16 + (lane >> 2);
#pragma unroll
        for (int nf = 0; nf < 4; nf++) {
            int n = warp_n * 32 + nf * 8 + (lane & 3) * 2;
            float2 bb = *(const float2*)(bias + n0 + n);
            float2 s0 = make_float2(acc[mf][nf][0] + bb.x, acc[mf][nf][1] + bb.y);
            float2 s1 = make_float2(acc[mf][nf][2] + bb.x, acc[mf][nf][3] + bb.y);
            if (RES) {
                if (m0 + mrow < M) {
                    float2 r = *(const float2*)(Rm + (long)(m0 + mrow) * ldc + n0 + n);
                    s0.x += r.x; s0.y += r.y;
                }
                if (m0 + mrow + 8 < M) {
                    float2 r = *(const float2*)(Rm + (long)(m0 + mrow + 8) * ldc + n0 + n);
                    s1.x += r.x; s1.y += r.y;
                }
            }
            if (m0 + mrow < M)
                *(float2*)(C + (long)(m0 + mrow) * ldc + n0 + n) = s0;
            if (m0 + mrow + 8 < M)
                *(float2*)(C + (long)(m0 + mrow + 8) * ldc + n0 + n) = s1;
        }
    }
}

template <bool RES>
__global__ void __launch_bounds__(256) gemm_small(
    const float* __restrict__ A, const float* __restrict__ Bm,
    const float* __restrict__ bias, const float* __restrict__ Rm,
    float* __restrict__ C, int M, int ldb, int ldc)
{
    extern __shared__ char smem[];
    gemm_core<RES>(A, Bm, bias, Rm, C, M, blockIdx.x * 128, blockIdx.y * 64,
                   ldb, ldc, smem);
}

// prep gemms + fused biases in one wave
__global__ void __launch_bounds__(256) prep_gemm(
    const float* __restrict__ Wmo, const float* __restrict__ Wq,
    const float* __restrict__ Wo,
    const float* __restrict__ bq, const float* __restrict__ bmo,
    const float* __restrict__ bo, const float* __restrict__ boff,
    const float* __restrict__ battn)
{
    extern __shared__ char smem[];
    int bx = blockIdx.x;
    if (bx < 8) {
        gemm_core<false>(Wmo, Wo, g_zero, nullptr, g_w2, DD,
                         (bx & 1) * 128, (bx >> 1) * 64, DD, DD, smem);
    } else if (bx < 16) {
        bx -= 8;
        gemm_core<false>(Wq, Wo, g_zero, nullptr, g_w3, DD,
                         (bx & 1) * 128, (bx >> 1) * 64, DD, DD, smem);
    } else if (bx < 20) {
        bx -= 16;
        gemm_core<false>(Wq, g_woa, g_zero, nullptr, g_wf, DD,
                         0, bx * 64, 128, 128, smem);
    } else {
        const int lane = threadIdx.x & 31;
        const int n = (bx - 20) * 8 + (threadIdx.x >> 5);   // 0..383
        float s = 0.f;
        if (n < 256) {
#pragma unroll
            for (int i = 0; i < 8; i++) {
                int k = lane + i * 32;
                s = fmaf(bq[k] + bmo[k], Wo[k * DD + n], s);
            }
        } else {
            int nn = n - 256;
#pragma unroll
            for (int i = 0; i < 8; i++) {
                int k = lane + i * 32;
                s = fmaf(bq[k], g_woa[k * 128 + nn], s);
            }
        }
#pragma unroll
        for (int d = 16; d > 0; d >>= 1)
            s += __shfl_xor_sync(0xffffffffu, s, d);
        if (lane == 0) {
            if (n < 256) {
                g_b2[n] = s + bo[n];
            } else {
                int nn = n - 256;
                float b = (nn < 64) ? boff[nn] : (nn < 96 ? battn[nn - 64] : 0.f);
                g_bf[nn] = s + b;
            }
        }
    }
}

// =====================================================================
// gemm_v body: v[b,m,:] = bev^T[b,m,:] @ WvT^T + bv (HMMA fp16, fp32 acc)
// =====================================================================
#define VA_OFF        0                                     // 32768 bytes
#define VB(buf)       (32768 + (buf) * 16384)               // ..65536
#define V_STG         32768                                 // epilogue stage
#define V_SMEM 66560

__device__ __forceinline__ void gemm_v_body(
    char* smem, const float* __restrict__ bev, const float* __restrict__ bias,
    int m0, int b)
{
    const uint32_t sb = smem_u32(smem);
    const int tid = threadIdx.x;
    const int lane = tid & 31;
    const int wid = tid >> 5;
    const int warp_m = wid & 1;
    const int warp_n = wid >> 1;

    const float* Ag = bev + (long)b * CH * HWSZ + m0;

    uint32_t b_dst_off[4], b_goff[4];
#pragma unroll
    for (int p = 0; p < 4; p++) {
        int e = tid + p * 256;
        int n = e >> 2, c = e & 3;
        b_dst_off[p] = (uint32_t)(n * 64 + ((c ^ ((n >> 1) & 3)) << 4));
        b_goff[p] = (uint32_t)(n * 256 + c * 8);
    }

#pragma unroll
    for (int p = 0; p < 4; p++)
        CP16(sb + VB(0) + b_dst_off[p], (const void*)(g_bhi + b_goff[p]));
    CP_COMMIT();

#pragma unroll 4
    for (int p = 0; p < 16; p++) {
        int idx = tid + p * 256;
        int k = idx >> 4;
        int m4 = (idx & 15) << 2;
        float4 v = *(const float4*)(Ag + (long)k * HWSZ + m4);
        int c = m4 >> 3;
        uint32_t off = (uint32_t)(k * 128 + ((c ^ (k & 7)) << 4) + ((m4 & 4) << 1));
        *(uint2*)(smem + VA_OFF + off) = make_uint2(
            h2u(__float2half(v.x), __float2half(v.y)),
            h2u(__float2half(v.z), __float2half(v.w)));
    }

    const int tile = lane >> 3;
    const int kl = (lane & 7) + ((tile & 2) << 2);
    uint32_t aoff[2];
#pragma unroll
    for (int mf = 0; mf < 2; mf++) {
        int c = (warp_m * 32 + mf * 16 + ((tile & 1) << 3)) >> 3;
        aoff[mf] = (uint32_t)(kl * 128 + (((c ^ (kl & 7)) & 7) << 4));
    }
    uint32_t boff[4];
#pragma unroll
    for (int q = 0; q < 4; q++) {
        int n = warp_n * 64 + q * 16 + ((tile & 1) << 3) + (lane & 7);
        int c = (tile & 2) >> 1;
        boff[q] = (uint32_t)(n * 64 + ((c ^ ((n >> 1) & 3)) << 4));
    }

    float acc[2][8][4];
#pragma unroll
    for (int i = 0; i < 2; i++)
#pragma unroll
        for (int j = 0; j < 8; j++)
#pragma unroll
            for (int r = 0; r < 4; r++) acc[i][j][r] = 0.f;

    CP_WAIT0();
    __syncthreads();

    for (int kc = 0; kc < 8; kc++) {
        const int cur = kc & 1;
        if (kc < 7) {
            const uint32_t k0 = (uint32_t)((kc + 1) * 32);
#pragma unroll
            for (int p = 0; p < 4; p++)
                CP16(sb + VB(1 - cur) + b_dst_off[p], (const void*)(g_bhi + b_goff[p] + k0));
            CP_COMMIT();
        }

        const uint32_t Bh = sb + VB(cur);
#pragma unroll
        for (int ks = 0; ks < 2; ks++) {
            uint32_t a[2][4];
            const uint32_t akc = (uint32_t)((kc * 32 + ks * 16) * 128);
#pragma unroll
            for (int mf = 0; mf < 2; mf++)
                LDSM_T(a[mf], sb + VA_OFF + akc + aoff[mf]);

            const uint32_t ksx = (uint32_t)(ks << 5);
            uint32_t bh[2][4];
            LDSM(bh[0], Bh + (boff[0] ^ ksx));
#pragma unroll
            for (int q = 0; q < 4; q++) {
                const int bc = q & 1, bn_ = bc ^ 1;
                if (q < 3)
                    LDSM(bh[bn_], Bh + (boff[q + 1] ^ ksx));
#pragma unroll
                for (int h = 0; h < 2; h++) {
                    const int nf = q * 2 + h;
#pragma unroll
                    for (int mf = 0; mf < 2; mf++)
                        MMA_F16(acc[mf][nf], a[mf], bh[bc][h], bh[bc][h + 2]);
                }
            }
        }

        if (kc < 7) CP_WAIT0();
        __syncthreads();
    }

    char* stg = smem + V_STG;
#pragma unroll
    for (int mf = 0; mf < 2; mf++) {
        int mrow = warp_m * 32 + mf * 16 + (lane >> 2);
#pragma unroll
        for (int nf = 0; nf < 8; nf++) {
            int n = warp_n * 64 + nf * 8 + (lane & 3) * 2;
            float2 bb = *(const float2*)(bias + n);
            __half2 v0 = __floats2half2_rn(acc[mf][nf][0] + bb.x, acc[mf][nf][1] + bb.y);
            __half2 v1 = __floats2half2_rn(acc[mf][nf][2] + bb.x, acc[mf][nf][3] + bb.y);
            *(__half2*)(stg + mrow * 528 + n * 2) = v0;
            *(__half2*)(stg + (mrow + 8) * 528 + n * 2) = v1;
        }
    }
    __syncthreads();
    __half* vout = g_vh + ((long)b * HWSZ + m0) * DD;
#pragma unroll
    for (int i = 0; i < 8; i++) {
        int cid = tid + i * 256;
        int r = cid >> 5, c16 = cid & 31;
        *(uint4*)((char*)vout + (long)r * 512 + c16 * 16) =
            *(const uint4*)(stg + r * 528 + c16 * 16);
    }
}

// =====================================================================
// main_kernel: blocks 0..170 -> proj (qo / oa); blocks 171.. -> gemm_v
// =====================================================================
__global__ void __launch_bounds__(256, 2) main_kernel(
    const float* __restrict__ bev, const float* __restrict__ bias,
    const float* __restrict__ query)
{
    extern __shared__ char smem[];
    if (blockIdx.x < 171) {
        const int pid = blockIdx.x;
        const int bx = pid % 3, by = pid / 3;            // by 0..56
        if (bx < 2)
            gemm_core<false>(query, g_w3, g_b2, nullptr, g_qo, BB * NQ,
                             bx * 128, by * 64, DD, DD, smem);
        else
            gemm_core<false>(query, g_wf, g_bf, nullptr, g_oa, BB * NQ,
                             0, by * 64, 128, 128, smem);
    } else {
        const int bid = blockIdx.x - 171;
        gemm_v_body(smem, bev, bias, (bid % 625) * 64, bid / 625);
    }
}

// ---------------- Bezier + bilinear sampling + softmax + weighted sum ----------------
// (weight, idx) packed in one float2 -> single 8B LDS per gather.
__global__ __launch_bounds__(256) void sample_kernel(
    const float* __restrict__ ctrl, const float* __restrict__ pc)
{
    __shared__ float s_ctrl[8];
    __shared__ float s_off[64];
    __shared__ float s_aw[32];
    __shared__ float2 s_wi[320][4];     // .x = weight, .y = bitcast(idx*DD)

    const int bn = blockIdx.x;
    const int b = bn / NQ;
    const int tid = threadIdx.x;

    if (tid < 8)  s_ctrl[tid] = ctrl[(long)bn * 8 + tid];
    else if (tid >= 32 && tid < 96) s_off[tid - 32] = g_oa[(long)bn * 128 + (tid - 32)];
    else if (tid >= 96 && tid < 128) s_aw[tid - 96] = g_oa[(long)bn * 128 + 64 + (tid - 96)];
    __syncthreads();

    if (tid < 32) {
        float x = s_aw[tid];
        float m = x;
        m = fmaxf(m, __shfl_xor_sync(0xffffffffu, m, 1));
        m = fmaxf(m, __shfl_xor_sync(0xffffffffu, m, 2));
        float e = expf(x - m);
        float s = e;
        s += __shfl_xor_sync(0xffffffffu, s, 1);
        s += __shfl_xor_sync(0xffffffffu, s, 2);
        s_aw[tid] = e / s;
    }
    __syncthreads();

    const float p0 = pc[0], p1 = pc[1];
    const float invx = 1.f / (pc[3] - p0);
    const float invy = 1.f / (pc[4] - p1);

    for (int it = tid; it < 320; it += 256) {
        const int h = it / 40;
        const int kp = it - h * 40;
        const int k = kp >> 2;
        const int p = kp & 3;

        float t = (float)k * (1.0f / (NK - 1));
        float u = 1.f - t;
        float b0 = u * u * u, b1 = 3.f * u * u * t, b2 = 3.f * u * t * t, b3 = t * t * t;
        float px = b0 * s_ctrl[0] + b1 * s_ctrl[2] + b2 * s_ctrl[4] + b3 * s_ctrl[6];
        float py = b0 * s_ctrl[1] + b1 * s_ctrl[3] + b2 * s_ctrl[5] + b3 * s_ctrl[7];
        float nx = fminf(fmaxf((px - p0) * invx, 0.01f), 0.99f);
        float ny = fminf(fmaxf((py - p1) * invy, 0.01f), 0.99f);

        float gx = (nx + s_off[h * 8 + p * 2 + 0] * (1.f / WW)) * WW - 0.5f;
        float gy = (ny + s_off[h * 8 + p * 2 + 1] * (1.f / HH)) * HH - 0.5f;
        float fx = floorf(gx), fy = floorf(gy);
        float wx = gx - fx, wy = gy - fy;
        int xi = (int)fx, yi = (int)fy;
        float ap = s_aw[h * 4 + p];

#pragma unroll
        for (int c = 0; c < 4; c++) {
            int dx = c & 1, dy = c >> 1;
            int ix = xi + dx, iy = yi + dy;
            bool valid = (ix >= 0) & (ix < WW) & (iy >= 0) & (iy < HH);
            float wgt = valid ? ap * (dx ? wx : 1.f - wx) * (dy ? wy : 1.f - wy) : 0.f;
            int cx = min(max(ix, 0), WW - 1);
            int cy = min(max(iy, 0), HH - 1);
            s_wi[it][c] = make_float2(wgt, __int_as_float((cy * WW + cx) * DD));
        }
    }
    __syncthreads();

    // gather: warp = head; half-warp = entry parity; lane -> 2 channels (half2)
    const int h = tid >> 5, lane = tid & 31;
    const int hw = lane >> 4, sl = lane & 15;
    const __half* vb = g_vh + (long)b * HWSZ * DD + h * HDIM + sl * 2;
    const float2* wirow = &s_wi[h * 40][0];
    float ax = 0.f, ay = 0.f;
#pragma unroll 8
    for (int eb = 0; eb < 80; eb++) {
        const int e = eb * 2 + hw;
        float2 wi = wirow[e];
        float w = wi.x;
        int idx = __float_as_int(wi.y);
        __half2 hv = *(const __half2*)(vb + idx);
        float2 f = __half22float2(hv);
        ax = fmaf(w, f.x, ax);
        ay = fmaf(w, f.y, ay);
    }
    ax += __shfl_down_sync(0xffffffffu, ax, 16);
    ay += __shfl_down_sync(0xffffffffu, ay, 16);
    if (hw == 0)
        *(float2*)(g_s + (long)bn * DD + h * HDIM + sl * 2) = make_float2(ax, ay);
}

// ---------------- launch ----------------
extern "C" void kernel_launch(void* const* d_in, const int* in_sizes, int n_in,
                              void* d_out, int out_size)
{
    const float* query = (const float*)d_in[0];
    const float* ctrl  = (const float*)d_in[1];
    const float* bev   = (const float*)d_in[2];
    const float* pc    = (const float*)d_in[4];
    const float* Wq    = (const float*)d_in[5];
    const float* bq    = (const float*)d_in[6];
    const float* Wv    = (const float*)d_in[7];
    const float* bv    = (const float*)d_in[8];
    const float* Woff  = (const float*)d_in[9];
    const float* boff  = (const float*)d_in[10];
    const float* Wattn = (const float*)d_in[11];
    const float* battn = (const float*)d_in[12];
    const float* Wmo   = (const float*)d_in[13];
    const float* bmo   = (const float*)d_in[14];
    const float* Wo    = (const float*)d_in[15];
    const float* bo    = (const float*)d_in[16];
    float* out = (float*)d_out;

    float *ps, *pqo, *pw2, *pzero;
    cudaGetSymbolAddress((void**)&ps, g_s);
    cudaGetSymbolAddress((void**)&pqo, g_qo);
    cudaGetSymbolAddress((void**)&pw2, g_w2);
    cudaGetSymbolAddress((void**)&pzero, g_zero);

    cudaFuncSetAttribute(main_kernel, cudaFuncAttributeMaxDynamicSharedMemorySize, V_SMEM);
    cudaFuncSetAttribute(gemm_small<true>, cudaFuncAttributeMaxDynamicSharedMemorySize, S_SMEM);
    cudaFuncSetAttribute(prep_gemm, cudaFuncAttributeMaxDynamicSharedMemorySize, S_SMEM);

    const int Mq = BB * NQ;                     // 3600

    // Wv conversion + [Woff|Wattn|0] packing
    prep_kernel<<<384, 256>>>(Wv, Woff, Wattn);
    // W2, W3, Wf gemms + fused biases in one wave
    prep_gemm<<<68, 256, S_SMEM>>>(Wmo, Wq, Wo, bq, bmo, bo, boff, battn);

    // merged: proj (qo, oa) + gemm_v (v) in one grid
    main_kernel<<<171 + (HWSZ / 64) * BB, 256, V_SMEM>>>(bev, bv, query);

    // bezier + softmax + bilinear sampling + attention-weighted sum
    sample_kernel<<<BB * NQ, 256>>>(ctrl, pc);

    // out = s@W2 + qo   (single fused tail gemm)
    gemm_small<true><<<dim3(2, (Mq + 63) / 64), 256, S_SMEM>>>(
        ps, pw2, pzero, pqo, out, Mq, DD, DD);
}

// round 17
// speedup vs baseline: 1.2843x; 1.0376x over previous
#include <cuda_runtime.h>
#include <cuda_bf16.h>
#include <cuda_fp16.h>
#include <cstdint>
#include <math.h>

// Problem constants (fixed shapes)
#define BB      4
#define NQ      900
#define DD      256
#define CH      256
#define HH      200
#define WW      200
#define HWSZ    40000
#define NHEADS  8
#define HDIM    32
#define NK      10
#define NPTS    4

// ---------------- scratch (device globals; no runtime allocation) ----------------
__device__ __half g_vh[(long)BB * HWSZ * DD];    // projected BEV values (fp16)
__device__ float g_oa [BB * NQ * 128];           // fused offsets(64)+attn logits(32)+pad
__device__ float g_qo [BB * NQ * DD];            // query@W3 + b2 (residual-through-Wo)
__device__ float g_s  [BB * NQ * DD];
__device__ __half g_bhi[DD * CH];                // WvT [n][k] fp16
__device__ float g_woa[DD * 128];                // packed [Woff | Wattn | 0] fp32 [k][n]
__device__ float g_wf [DD * 128];                // Wq @ woa  [k][n]
__device__ float g_w2 [DD * DD];                 // Wmo @ Wo
__device__ float g_w3 [DD * DD];                 // Wq @ Wo
__device__ float g_bf [128];                     // bq @ woa + [boff|battn|0]
__device__ float g_b2 [DD];                      // (bq+bmo) @ Wo + bo
__device__ float g_zero[DD];                     // stays zero

// ---------------- helpers ----------------
__device__ __forceinline__ uint32_t smem_u32(const void* p) {
    uint32_t a;
    asm("{ .reg .u64 t; cvta.to.shared.u64 t, %1; cvt.u32.u64 %0, t; }" : "=r"(a) : "l"(p));
    return a;
}
__device__ __forceinline__ uint32_t bf2u(__nv_bfloat16 a, __nv_bfloat16 b) {
    __nv_bfloat162 t(a, b);
    return *reinterpret_cast<uint32_t*>(&t);
}
__device__ __forceinline__ uint32_t h2u(__half a, __half b) {
    __half2 t(a, b);
    return *reinterpret_cast<uint32_t*>(&t);
}

#define LDSM_T(r, addr) \
    asm volatile("ldmatrix.sync.aligned.m8n8.x4.trans.shared.b16 {%0,%1,%2,%3}, [%4];" \
        : "=r"((r)[0]), "=r"((r)[1]), "=r"((r)[2]), "=r"((r)[3]) : "r"(addr))
#define LDSM(r, addr) \
    asm volatile("ldmatrix.sync.aligned.m8n8.x4.shared.b16 {%0,%1,%2,%3}, [%4];" \
        : "=r"((r)[0]), "=r"((r)[1]), "=r"((r)[2]), "=r"((r)[3]) : "r"(addr))
#define MMA_BF16(c, a, b0, b1) \
    asm volatile("mma.sync.aligned.m16n8k16.row.col.f32.bf16.bf16.f32 " \
        "{%0,%1,%2,%3},{%4,%5,%6,%7},{%8,%9},{%0,%1,%2,%3};" \
        : "+f"((c)[0]), "+f"((c)[1]), "+f"((c)[2]), "+f"((c)[3]) \
        : "r"((a)[0]), "r"((a)[1]), "r"((a)[2]), "r"((a)[3]), "r"(b0), "r"(b1))
#define MMA_F16(c, a, b0, b1) \
    asm volatile("mma.sync.aligned.m16n8k16.row.col.f32.f16.f16.f32 " \
        "{%0,%1,%2,%3},{%4,%5,%6,%7},{%8,%9},{%0,%1,%2,%3};" \
        : "+f"((c)[0]), "+f"((c)[1]), "+f"((c)[2]), "+f"((c)[3]) \
        : "r"((a)[0]), "r"((a)[1]), "r"((a)[2]), "r"((a)[3]), "r"(b0), "r"(b1))
#define CP16(dst, src) \
    asm volatile("cp.async.cg.shared.global [%0], [%1], 16;" :: "r"(dst), "l"(src))
#define CP_COMMIT()  asm volatile("cp.async.commit_group;" ::: "memory")
#define CP_WAIT0()   asm volatile("cp.async.wait_group 0;" ::: "memory")

__device__ __forceinline__ void split_store(char* dst_h, char* dst_l, uint32_t off, float4 v) {
    __nv_bfloat16 h0 = __float2bfloat16(v.x), h1 = __float2bfloat16(v.y);
    __nv_bfloat16 h2 = __float2bfloat16(v.z), h3 = __float2bfloat16(v.w);
    __nv_bfloat16 l0 = __float2bfloat16(v.x - __bfloat162float(h0));
    __nv_bfloat16 l1 = __float2bfloat16(v.y - __bfloat162float(h1));
    __nv_bfloat16 l2 = __float2bfloat16(v.z - __bfloat162float(h2));
    __nv_bfloat16 l3 = __float2bfloat16(v.w - __bfloat162float(h3));
    *(uint2*)(dst_h + off) = make_uint2(bf2u(h0, h1), bf2u(h2, h3));
    *(uint2*)(dst_l + off) = make_uint2(bf2u(l0, l1), bf2u(l2, l3));
}

// ---------------- pack [Woff | Wattn | 0] -> g_woa ----------------
__global__ __launch_bounds__(256) void pack_woa(
    const float* __restrict__ Woff, const float* __restrict__ Wattn)
{
    int idx = blockIdx.x * 256 + threadIdx.x;   // 0..32767
    int k = idx >> 7, n = idx & 127;
    g_woa[idx] = (n < 64) ? Woff[k * 64 + n] : (n < 96 ? Wattn[k * 32 + (n - 64)] : 0.f);
}

// =====================================================================
// gemm_core: C[m0.., n0..n0+128] = A[M x 256] @ B[256 x ldb] + bias (+R)
// bf16 3-term split, CTA 64 x 128, 8 warps = 2m x 4n. SINGLE-buffered.
// =====================================================================
#define S_APITCH 72
#define S_BPITCH 136
#define S_AB(hl) ((hl) * 9216)                   // 0, 9216
#define S_BB(hl) (18432 + (hl) * 17408)          // 18432, 35840
#define S_SMEM 53248

template <bool RES>
__device__ __forceinline__ void gemm_core(
    const float* __restrict__ A, const float* __restrict__ Bm,
    const float* __restrict__ bias, const float* __restrict__ Rm,
    float* __restrict__ C, int M, int n0, int m0, int ldb, int ldc,
    char* smem)
{
    const uint32_t sb = smem_u32(smem);
    const int tid = threadIdx.x;
    const int lane = tid & 31;
    const int wid = tid >> 5;
    const int warp_m = wid & 1;
    const int warp_n = wid >> 1;

    const int tile = lane >> 3;
    uint32_t aoff[2];
#pragma unroll
    for (int mf = 0; mf < 2; mf++) {
        int ml = warp_m * 32 + mf * 16 + ((tile & 1) << 3) + (lane & 7);
        int kcol = (tile & 2) << 2;
        aoff[mf] = (uint32_t)(ml * S_APITCH + kcol) * 2;
    }
    uint32_t boff[2];
#pragma unroll
    for (int q = 0; q < 2; q++) {
        int kr = (lane & 7) + ((tile & 2) << 2);
        int nc = warp_n * 32 + q * 16 + ((tile & 1) << 3);
        boff[q] = (uint32_t)(kr * S_BPITCH + nc) * 2;
    }

    float acc[2][4][4];
#pragma unroll
    for (int i = 0; i < 2; i++)
#pragma unroll
        for (int j = 0; j < 4; j++)
#pragma unroll
            for (int r = 0; r < 4; r++) acc[i][j][r] = 0.f;

    float4 rA[4], rB[8];

    for (int kc = 0; kc < 4; kc++) {
        const int k0 = kc * 64;
#pragma unroll
        for (int p = 0; p < 4; p++) {
            int idx = tid + p * 256;
            int m = idx >> 4, k4 = (idx & 15) << 2;
            rA[p] = (m0 + m < M) ? *(const float4*)(A + (long)(m0 + m) * DD + k0 + k4)
                                 : make_float4(0.f, 0.f, 0.f, 0.f);
        }
#pragma unroll
        for (int p = 0; p < 8; p++) {
            int idx = tid + p * 256;
            int k = idx >> 5, n4 = (idx & 31) << 2;
            rB[p] = *(const float4*)(Bm + (long)(k0 + k) * ldb + n0 + n4);
        }
        if (kc) __syncthreads();
#pragma unroll
        for (int p = 0; p < 4; p++) {
            int idx = tid + p * 256;
            int m = idx >> 4, k4 = (idx & 15) << 2;
            split_store(smem + S_AB(0), smem + S_AB(1),
                        (uint32_t)(m * S_APITCH + k4) * 2, rA[p]);
        }
#pragma unroll
        for (int p = 0; p < 8; p++) {
            int idx = tid + p * 256;
            int k = idx >> 5, n4 = (idx & 31) << 2;
            split_store(smem + S_BB(0), smem + S_BB(1),
                        (uint32_t)(k * S_BPITCH + n4) * 2, rB[p]);
        }
        __syncthreads();

        const uint32_t Ah = sb + S_AB(0), Al = sb + S_AB(1);
        const uint32_t Bh = sb + S_BB(0), Bl = sb + S_BB(1);
#pragma unroll
        for (int ks = 0; ks < 4; ks++) {
            uint32_t ah[2][4], al[2][4], bh[2][4], bl[2][4];
#pragma unroll
            for (int mf = 0; mf < 2; mf++) {
                LDSM(ah[mf], Ah + aoff[mf] + ks * 32);
                LDSM(al[mf], Al + aoff[mf] + ks * 32);
            }
#pragma unroll
            for (int q = 0; q < 2; q++) {
                LDSM_T(bh[q], Bh + boff[q] + ks * (16 * S_BPITCH * 2));
                LDSM_T(bl[q], Bl + boff[q] + ks * (16 * S_BPITCH * 2));
            }
#pragma unroll
            for (int mf = 0; mf < 2; mf++)
#pragma unroll
                for (int nf = 0; nf < 4; nf++) {
                    int q = nf >> 1, h = nf & 1;
                    MMA_BF16(acc[mf][nf], ah[mf], bh[q][h], bh[q][h + 2]);
                    MMA_BF16(acc[mf][nf], ah[mf], bl[q][h], bl[q][h + 2]);
                    MMA_BF16(acc[mf][nf], al[mf], bh[q][h], bh[q][h + 2]);
                }
        }
    }

#pragma unroll
    for (int mf = 0; mf < 2; mf++) {
        int mrow = warp_m * 32 + mf * 16 + (lane >> 2);
#pragma unroll
        for (int nf = 0; nf < 4; nf++) {
            int n = warp_n * 32 + nf * 8 + (lane & 3) * 2;
            float2 bb = *(const float2*)(bias + n0 + n);
            float2 s0 = make_float2(acc[mf][nf][0] + bb.x, acc[mf][nf][1] + bb.y);
            float2 s1 = make_float2(acc[mf][nf][2] + bb.x, acc[mf][nf][3] + bb.y);
            if (RES) {
                if (m0 + mrow < M) {
                    float2 r = *(const float2*)(Rm + (long)(m0 + mrow) * ldc + n0 + n);
                    s0.x += r.x; s0.y += r.y;
                }
                if (m0 + mrow + 8 < M) {
                    float2 r = *(const float2*)(Rm + (long)(m0 + mrow + 8) * ldc + n0 + n);
                    s1.x += r.x; s1.y += r.y;
                }
            }
            if (m0 + mrow < M)
                *(float2*)(C + (long)(m0 + mrow) * ldc + n0 + n) = s0;
            if (m0 + mrow + 8 < M)
                *(float2*)(C + (long)(m0 + mrow + 8) * ldc + n0 + n) = s1;
        }
    }
}

template <bool RES>
__global__ void __launch_bounds__(256) gemm_small(
    const float* __restrict__ A, const float* __restrict__ Bm,
    const float* __restrict__ bias, const float* __restrict__ Rm,
    float* __restrict__ C, int M, int ldb, int ldc)
{
    extern __shared__ char smem[];
    gemm_core<RES>(A, Bm, bias, Rm, C, M, blockIdx.x * 128, blockIdx.y * 64,
                   ldb, ldc, smem);
}

// prep gemms + fused biases + Wv->fp16 conversion in one wave:
//   bx 0-7:  W2 = Wmo@Wo    bx 8-15: W3 = Wq@Wo    bx 16-19: Wf = Wq@woa
//   bx 20-67: biases        bx 68-323: g_bhi = WvT fp16
__global__ void __launch_bounds__(256) prep_gemm(
    const float* __restrict__ Wmo, const float* __restrict__ Wq,
    const float* __restrict__ Wo, const float* __restrict__ Wv,
    const float* __restrict__ bq, const float* __restrict__ bmo,
    const float* __restrict__ bo, const float* __restrict__ boff,
    const float* __restrict__ battn)
{
    extern __shared__ char smem[];
    int bx = blockIdx.x;
    if (bx < 8) {
        gemm_core<false>(Wmo, Wo, g_zero, nullptr, g_w2, DD,
                         (bx & 1) * 128, (bx >> 1) * 64, DD, DD, smem);
    } else if (bx < 16) {
        bx -= 8;
        gemm_core<false>(Wq, Wo, g_zero, nullptr, g_w3, DD,
                         (bx & 1) * 128, (bx >> 1) * 64, DD, DD, smem);
    } else if (bx < 20) {
        bx -= 16;
        gemm_core<false>(Wq, g_woa, g_zero, nullptr, g_wf, DD,
                         0, bx * 64, 128, 128, smem);
    } else if (bx < 68) {
        const int lane = threadIdx.x & 31;
        const int n = (bx - 20) * 8 + (threadIdx.x >> 5);   // 0..383
        float s = 0.f;
        if (n < 256) {
#pragma unroll
            for (int i = 0; i < 8; i++) {
                int k = lane + i * 32;
                s = fmaf(bq[k] + bmo[k], Wo[k * DD + n], s);
            }
        } else {
            int nn = n - 256;
#pragma unroll
            for (int i = 0; i < 8; i++) {
                int k = lane + i * 32;
                s = fmaf(bq[k], g_woa[k * 128 + nn], s);
            }
        }
#pragma unroll
        for (int d = 16; d > 0; d >>= 1)
            s += __shfl_xor_sync(0xffffffffu, s, d);
        if (lane == 0) {
            if (n < 256) {
                g_b2[n] = s + bo[n];
            } else {
                int nn = n - 256;
                float b = (nn < 64) ? boff[nn] : (nn < 96 ? battn[nn - 64] : 0.f);
                g_bf[nn] = s + b;
            }
        }
    } else {
        int idx = (bx - 68) * 256 + threadIdx.x;   // n*256 + k
        int n = idx >> 8, k = idx & 255;
        g_bhi[idx] = __float2half(Wv[k * DD + n]);
    }
}

// =====================================================================
// gemm_v body: v[b,m,:] = bev^T[b,m,:] @ WvT^T + bv (HMMA fp16, fp32 acc)
// =====================================================================
#define VA_OFF        0                                     // 32768 bytes
#define VB(buf)       (32768 + (buf) * 16384)               // ..65536
#define V_STG         32768                                 // epilogue stage
#define V_SMEM 66560

__device__ __forceinline__ void gemm_v_body(
    char* smem, const float* __restrict__ bev, const float* __restrict__ bias,
    int m0, int b)
{
    const uint32_t sb = smem_u32(smem);
    const int tid = threadIdx.x;
    const int lane = tid & 31;
    const int wid = tid >> 5;
    const int warp_m = wid & 1;
    const int warp_n = wid >> 1;

    const float* Ag = bev + (long)b * CH * HWSZ + m0;

    uint32_t b_dst_off[4], b_goff[4];
#pragma unroll
    for (int p = 0; p < 4; p++) {
        int e = tid + p * 256;
        int n = e >> 2, c = e & 3;
        b_dst_off[p] = (uint32_t)(n * 64 + ((c ^ ((n >> 1) & 3)) << 4));
        b_goff[p] = (uint32_t)(n * 256 + c * 8);
    }

#pragma unroll
    for (int p = 0; p < 4; p++)
        CP16(sb + VB(0) + b_dst_off[p], (const void*)(g_bhi + b_goff[p]));
    CP_COMMIT();

#pragma unroll 4
    for (int p = 0; p < 16; p++) {
        int idx = tid + p * 256;
        int k = idx >> 4;
        int m4 = (idx & 15) << 2;
        float4 v = *(const float4*)(Ag + (long)k * HWSZ + m4);
        int c = m4 >> 3;
        uint32_t off = (uint32_t)(k * 128 + ((c ^ (k & 7)) << 4) + ((m4 & 4) << 1));
        *(uint2*)(smem + VA_OFF + off) = make_uint2(
            h2u(__float2half(v.x), __float2half(v.y)),
            h2u(__float2half(v.z), __float2half(v.w)));
    }

    const int tile = lane >> 3;
    const int kl = (lane & 7) + ((tile & 2) << 2);
    uint32_t aoff[2];
#pragma unroll
    for (int mf = 0; mf < 2; mf++) {
        int c = (warp_m * 32 + mf * 16 + ((tile & 1) << 3)) >> 3;
        aoff[mf] = (uint32_t)(kl * 128 + (((c ^ (kl & 7)) & 7) << 4));
    }
    uint32_t boff[4];
#pragma unroll
    for (int q = 0; q < 4; q++) {
        int n = warp_n * 64 + q * 16 + ((tile & 1) << 3) + (lane & 7);
        int c = (tile & 2) >> 1;
        boff[q] = (uint32_t)(n * 64 + ((c ^ ((n >> 1) & 3)) << 4));
    }

    float acc[2][8][4];
#pragma unroll
    for (int i = 0; i < 2; i++)
#pragma unroll
        for (int j = 0; j < 8; j++)
#pragma unroll
            for (int r = 0; r < 4; r++) acc[i][j][r] = 0.f;

    CP_WAIT0();
    __syncthreads();

    for (int kc = 0; kc < 8; kc++) {
        const int cur = kc & 1;
        if (kc < 7) {
            const uint32_t k0 = (uint32_t)((kc + 1) * 32);
#pragma unroll
            for (int p = 0; p < 4; p++)
                CP16(sb + VB(1 - cur) + b_dst_off[p], (const void*)(g_bhi + b_goff[p] + k0));
            CP_COMMIT();
        }

        const uint32_t Bh = sb + VB(cur);
#pragma unroll
        for (int ks = 0; ks < 2; ks++) {
            uint32_t a[2][4];
            const uint32_t akc = (uint32_t)((kc * 32 + ks * 16) * 128);
#pragma unroll
            for (int mf = 0; mf < 2; mf++)
                LDSM_T(a[mf], sb + VA_OFF + akc + aoff[mf]);

            const uint32_t ksx = (uint32_t)(ks << 5);
            uint32_t bh[2][4];
            LDSM(bh[0], Bh + (boff[0] ^ ksx));
#pragma unroll
            for (int q = 0; q < 4; q++) {
                const int bc = q & 1, bn_ = bc ^ 1;
                if (q < 3)
                    LDSM(bh[bn_], Bh + (boff[q + 1] ^ ksx));
#pragma unroll
                for (int h = 0; h < 2; h++) {
                    const int nf = q * 2 + h;
#pragma unroll
                    for (int mf = 0; mf < 2; mf++)
                        MMA_F16(acc[mf][nf], a[mf], bh[bc][h], bh[bc][h + 2]);
                }
            }
        }

        if (kc < 7) CP_WAIT0();
        __syncthreads();
    }

    char* stg = smem + V_STG;
#pragma unroll
    for (int mf = 0; mf < 2; mf++) {
        int mrow = warp_m * 32 + mf * 16 + (lane >> 2);
#pragma unroll
        for (int nf = 0; nf < 8; nf++) {
            int n = warp_n * 64 + nf * 8 + (lane & 3) * 2;
            float2 bb = *(const float2*)(bias + n);
            __half2 v0 = __floats2half2_rn(acc[mf][nf][0] + bb.x, acc[mf][nf][1] + bb.y);
            __half2 v1 = __floats2half2_rn(acc[mf][nf][2] + bb.x, acc[mf][nf][3] + bb.y);
            *(__half2*)(stg + mrow * 528 + n * 2) = v0;
            *(__half2*)(stg + (mrow + 8) * 528 + n * 2) = v1;
        }
    }
    __syncthreads();
    __half* vout = g_vh + ((long)b * HWSZ + m0) * DD;
#pragma unroll
    for (int i = 0; i < 8; i++) {
        int cid = tid + i * 256;
        int r = cid >> 5, c16 = cid & 31;
        *(uint4*)((char*)vout + (long)r * 512 + c16 * 16) =
            *(const uint4*)(stg + r * 528 + c16 * 16);
    }
}

// =====================================================================
// main_kernel: blocks 0..170 -> proj (qo / oa); blocks 171.. -> gemm_v
// =====================================================================
__global__ void __launch_bounds__(256, 2) main_kernel(
    const float* __restrict__ bev, const float* __restrict__ bias,
    const float* __restrict__ query)
{
    extern __shared__ char smem[];
    if (blockIdx.x < 171) {
        const int pid = blockIdx.x;
        const int bx = pid % 3, by = pid / 3;            // by 0..56
        if (bx < 2)
            gemm_core<false>(query, g_w3, g_b2, nullptr, g_qo, BB * NQ,
                             bx * 128, by * 64, DD, DD, smem);
        else
            gemm_core<false>(query, g_wf, g_bf, nullptr, g_oa, BB * NQ,
                             0, by * 64, 128, 128, smem);
    } else {
        const int bid = blockIdx.x - 171;
        gemm_v_body(smem, bev, bias, (bid % 625) * 64, bid / 625);
    }
}

// ---------------- Bezier + bilinear sampling + softmax + weighted sum ----------------
// Phase 2: warp = head; quarter-warp = entry slot (4 entries in flight);
// lane covers 4 channels via one LDG.64; reduce via shfl_xor(8,16).
__global__ __launch_bounds__(256) void sample_kernel(
    const float* __restrict__ ctrl, const float* __restrict__ pc)
{
    __shared__ float s_ctrl[8];
    __shared__ float s_off[64];
    __shared__ float s_aw[32];
    __shared__ float2 s_wi[320][4];     // .x = weight, .y = bitcast(idx*DD)

    const int bn = blockIdx.x;
    const int b = bn / NQ;
    const int tid = threadIdx.x;

    if (tid < 8)  s_ctrl[tid] = ctrl[(long)bn * 8 + tid];
    else if (tid >= 32 && tid < 96) s_off[tid - 32] = g_oa[(long)bn * 128 + (tid - 32)];
    else if (tid >= 96 && tid < 128) s_aw[tid - 96] = g_oa[(long)bn * 128 + 64 + (tid - 96)];
    __syncthreads();

    if (tid < 32) {
        float x = s_aw[tid];
        float m = x;
        m = fmaxf(m, __shfl_xor_sync(0xffffffffu, m, 1));
        m = fmaxf(m, __shfl_xor_sync(0xffffffffu, m, 2));
        float e = expf(x - m);
        float s = e;
        s += __shfl_xor_sync(0xffffffffu, s, 1);
        s += __shfl_xor_sync(0xffffffffu, s, 2);
        s_aw[tid] = e / s;
    }
    __syncthreads();

    const float p0 = pc[0], p1 = pc[1];
    const float invx = 1.f / (pc[3] - p0);
    const float invy = 1.f / (pc[4] - p1);

    for (int it = tid; it < 320; it += 256) {
        const int h = it / 40;
        const int kp = it - h * 40;
        const int k = kp >> 2;
        const int p = kp & 3;

        float t = (float)k * (1.0f / (NK - 1));
        float u = 1.f - t;
        float b0 = u * u * u, b1 = 3.f * u * u * t, b2 = 3.f * u * t * t, b3 = t * t * t;
        float px = b0 * s_ctrl[0] + b1 * s_ctrl[2] + b2 * s_ctrl[4] + b3 * s_ctrl[6];
        float py = b0 * s_ctrl[1] + b1 * s_ctrl[3] + b2 * s_ctrl[5] + b3 * s_ctrl[7];
        float nx = fminf(fmaxf((px - p0) * invx, 0.01f), 0.99f);
        float ny = fminf(fmaxf((py - p1) * invy, 0.01f), 0.99f);

        float gx = (nx + s_off[h * 8 + p * 2 + 0] * (1.f / WW)) * WW - 0.5f;
        float gy = (ny + s_off[h * 8 + p * 2 + 1] * (1.f / HH)) * HH - 0.5f;
        float fx = floorf(gx), fy = floorf(gy);
        float wx = gx - fx, wy = gy - fy;
        int xi = (int)fx, yi = (int)fy;
        float ap = s_aw[h * 4 + p];

#pragma unroll
        for (int c = 0; c < 4; c++) {
            int dx = c & 1, dy = c >> 1;
            int ix = xi + dx, iy = yi + dy;
            bool valid = (ix >= 0) & (ix < WW) & (iy >= 0) & (iy < HH);
            float wgt = valid ? ap * (dx ? wx : 1.f - wx) * (dy ? wy : 1.f - wy) : 0.f;
            int cx = min(max(ix, 0), WW - 1);
            int cy = min(max(iy, 0), HH - 1);
            s_wi[it][c] = make_float2(wgt, __int_as_float((cy * WW + cx) * DD));
        }
    }
    __syncthreads();

    // gather: warp = head; quarter-warp qw = entry slot; sl -> 4 channels
    const int h = tid >> 5, lane = tid & 31;
    const int qw = lane >> 3, sl = lane & 7;
    const __half* vb = g_vh + (long)b * HWSZ * DD + h * HDIM + sl * 4;
    const float2* wirow = &s_wi[h * 40][0];
    float a0 = 0.f, a1 = 0.f, a2 = 0.f, a3 = 0.f;
#pragma unroll 4
    for (int eb = 0; eb < 40; eb++) {
        const int e = eb * 4 + qw;
        float2 wi = wirow[e];
        float w = wi.x;
        int idx = __float_as_int(wi.y);
        uint2 hv = *(const uint2*)(vb + idx);
        float2 f0 = __half22float2(*reinterpret_cast<__half2*>(&hv.x));
        float2 f1 = __half22float2(*reinterpret_cast<__half2*>(&hv.y));
        a0 = fmaf(w, f0.x, a0);
        a1 = fmaf(w, f0.y, a1);
        a2 = fmaf(w, f1.x, a2);
        a3 = fmaf(w, f1.y, a3);
    }
    a0 += __shfl_xor_sync(0xffffffffu, a0, 8);
    a1 += __shfl_xor_sync(0xffffffffu, a1, 8);
    a2 += __shfl_xor_sync(0xffffffffu, a2, 8);
    a3 += __shfl_xor_sync(0xffffffffu, a3, 8);
    a0 += __shfl_xor_sync(0xffffffffu, a0, 16);
    a1 += __shfl_xor_sync(0xffffffffu, a1, 16);
    a2 += __shfl_xor_sync(0xffffffffu, a2, 16);
    a3 += __shfl_xor_sync(0xffffffffu, a3, 16);
    if (qw == 0)
        *(float4*)(g_s + (long)bn * DD + h * HDIM + sl * 4) = make_float4(a0, a1, a2, a3);
}

// ---------------- launch ----------------
extern "C" void kernel_launch(void* const* d_in, const int* in_sizes, int n_in,
                              void* d_out, int out_size)
{
    const float* query = (const float*)d_in[0];
    const float* ctrl  = (const float*)d_in[1];
    const float* bev   = (const float*)d_in[2];
    const float* pc    = (const float*)d_in[4];
    const float* Wq    = (const float*)d_in[5];
    const float* bq    = (const float*)d_in[6];
    const float* Wv    = (const float*)d_in[7];
    const float* bv    = (const float*)d_in[8];
    const float* Woff  = (const float*)d_in[9];
    const float* boff  = (const float*)d_in[10];
    const float* Wattn = (const float*)d_in[11];
    const float* battn = (const float*)d_in[12];
    const float* Wmo   = (const float*)d_in[13];
    const float* bmo   = (const float*)d_in[14];
    const float* Wo    = (const float*)d_in[15];
    const float* bo    = (const float*)d_in[16];
    float* out = (float*)d_out;

    float *ps, *pqo, *pw2, *pzero;
    cudaGetSymbolAddress((void**)&ps, g_s);
    cudaGetSymbolAddress((void**)&pqo, g_qo);
    cudaGetSymbolAddress((void**)&pw2, g_w2);
    cudaGetSymbolAddress((void**)&pzero, g_zero);

    cudaFuncSetAttribute(main_kernel, cudaFuncAttributeMaxDynamicSharedMemorySize, V_SMEM);
    cudaFuncSetAttribute(gemm_small<true>, cudaFuncAttributeMaxDynamicSharedMemorySize, S_SMEM);
    cudaFuncSetAttribute(prep_gemm, cudaFuncAttributeMaxDynamicSharedMemorySize, S_SMEM);

    const int Mq = BB * NQ;                     // 3600

    // pack [Woff|Wattn|0]
    pack_woa<<<128, 256>>>(Woff, Wattn);
    // W2, W3, Wf gemms + fused biases + Wv->fp16 in one wave
    prep_gemm<<<324, 256, S_SMEM>>>(Wmo, Wq, Wo, Wv, bq, bmo, bo, boff, battn);

    // merged: proj (qo, oa) + gemm_v (v) in one grid
    main_kernel<<<171 + (HWSZ / 64) * BB, 256, V_SMEM>>>(bev, bv, query);

    // bezier + softmax + bilinear sampling + attention-weighted sum
    sample_kernel<<<BB * NQ, 256>>>(ctrl, pc);

    // out = s@W2 + qo   (single fused tail gemm)
    gemm_small<true><<<dim3(2, (Mq + 63) / 64), 256, S_SMEM>>>(
        ps, pw2, pzero, pqo, out, Mq, DD, DD);
}